// round 5
// baseline (speedup 1.0000x reference)
#include <cuda_runtime.h>
#include <math.h>

// Problem constants
#define B_   4
#define S_   2048
#define D_   1024
#define H_   16
#define DK_  64
#define DFF_ 4096
#define NTOK (B_*S_)     // 8192 tokens
#define EPS_ 1e-5f

// ---------------------------------------------------------------------------
// Scratch (device globals: allocation-free, allowed by harness rules)
// ---------------------------------------------------------------------------
__device__ float g_h [(size_t)NTOK*D_];   // LN1 output
__device__ float g_q [(size_t)NTOK*D_];   // q projection (row-major [tok, h*64+dk])
__device__ float g_k [(size_t)NTOK*D_];
__device__ float g_v [(size_t)NTOK*D_];
__device__ float g_at[(size_t)NTOK*D_];   // attention output, token-major
__device__ float g_x1[(size_t)NTOK*D_];   // x + attn@wo
__device__ float g_h2[(size_t)NTOK*D_];   // LN2 output
__device__ float g_ff[(size_t)NTOK*DFF_]; // relu(h2@w1+b1)

// ---------------------------------------------------------------------------
// LayerNorm: one block per row (D=1024, 256 threads, 1 float4/thread)
// ---------------------------------------------------------------------------
__global__ void __launch_bounds__(256) ln_kernel(
    const float* __restrict__ x, const float* __restrict__ g,
    const float* __restrict__ b, float* __restrict__ out)
{
    int row = blockIdx.x;
    int tid = threadIdx.x;
    const float4* xr = (const float4*)(x + (size_t)row * D_);
    float4 xv = xr[tid];

    float s  = xv.x + xv.y + xv.z + xv.w;
    float ss = xv.x*xv.x + xv.y*xv.y + xv.z*xv.z + xv.w*xv.w;

    #pragma unroll
    for (int o = 16; o > 0; o >>= 1) {
        s  += __shfl_xor_sync(0xffffffffu, s,  o);
        ss += __shfl_xor_sync(0xffffffffu, ss, o);
    }
    __shared__ float sh_s[8], sh_ss[8];
    __shared__ float mu_sh, rs_sh;
    if ((tid & 31) == 0) { sh_s[tid >> 5] = s; sh_ss[tid >> 5] = ss; }
    __syncthreads();
    if (tid == 0) {
        float S = 0.f, SS = 0.f;
        #pragma unroll
        for (int i = 0; i < 8; i++) { S += sh_s[i]; SS += sh_ss[i]; }
        float mu  = S / (float)D_;
        float var = SS / (float)D_ - mu * mu;
        mu_sh = mu;
        rs_sh = rsqrtf(var + EPS_);
    }
    __syncthreads();
    float mu = mu_sh, rs = rs_sh;

    const float4* gr = (const float4*)g;
    const float4* br = (const float4*)b;
    float4 gv = gr[tid], bv = br[tid];
    float4 o;
    o.x = (xv.x - mu) * rs * gv.x + bv.x;
    o.y = (xv.y - mu) * rs * gv.y + bv.y;
    o.z = (xv.z - mu) * rs * gv.z + bv.z;
    o.w = (xv.w - mu) * rs * gv.w + bv.w;
    ((float4*)(out + (size_t)row * D_))[tid] = o;
}

// ---------------------------------------------------------------------------
// SGEMM: C[M,N] = epi(A[M,K] @ B[K,N]); BM=BN=128, BK=8, 256 threads, 8x8/thread
// EPI bit0 = +bias[n], bit1 = relu, bit2 = +res[m,n]
// Requires M%128==0, N%128==0, K%8==0 (true for all calls here).
// ---------------------------------------------------------------------------
template<int EPI>
__global__ void __launch_bounds__(256) sgemm_kernel(
    int M, int N, int K,
    const float* __restrict__ A, const float* __restrict__ Bm,
    const float* __restrict__ bias, const float* __restrict__ res,
    float* __restrict__ C)
{
    const int BM = 128, BN = 128, BK = 8;
    __shared__ float As[BK][BM];
    __shared__ float Bs[BK][BN];

    int tid = threadIdx.x;
    int m0 = blockIdx.y * BM;
    int n0 = blockIdx.x * BN;
    int tr = tid >> 4;          // 0..15 -> row micro-tile
    int tc = tid & 15;          // 0..15 -> col micro-tile

    float acc[8][8];
    #pragma unroll
    for (int i = 0; i < 8; i++)
        #pragma unroll
        for (int j = 0; j < 8; j++) acc[i][j] = 0.f;

    int aRow = tid >> 1;            // 0..127
    int aCol = (tid & 1) * 4;       // 0 or 4
    int bRow = tid >> 5;            // 0..7
    int bCol = (tid & 31) * 4;      // 0..124

    const float* Aptr = A + (size_t)(m0 + aRow) * K + aCol;
    const float* Bptr = Bm + (size_t)bRow * N + n0 + bCol;

    for (int k0 = 0; k0 < K; k0 += BK) {
        float4 av = *(const float4*)(Aptr + k0);
        float4 bv = *(const float4*)(Bptr + (size_t)k0 * N);
        As[aCol + 0][aRow] = av.x;
        As[aCol + 1][aRow] = av.y;
        As[aCol + 2][aRow] = av.z;
        As[aCol + 3][aRow] = av.w;
        *(float4*)&Bs[bRow][bCol] = bv;
        __syncthreads();

        #pragma unroll
        for (int kk = 0; kk < BK; kk++) {
            float a[8], b[8];
            *(float4*)(a)     = *(float4*)&As[kk][tr * 8];
            *(float4*)(a + 4) = *(float4*)&As[kk][tr * 8 + 4];
            *(float4*)(b)     = *(float4*)&Bs[kk][tc * 8];
            *(float4*)(b + 4) = *(float4*)&Bs[kk][tc * 8 + 4];
            #pragma unroll
            for (int i = 0; i < 8; i++)
                #pragma unroll
                for (int j = 0; j < 8; j++)
                    acc[i][j] += a[i] * b[j];
        }
        __syncthreads();
    }

    #pragma unroll
    for (int i = 0; i < 8; i++) {
        int m = m0 + tr * 8 + i;
        size_t off = (size_t)m * N + n0 + tc * 8;
        #pragma unroll
        for (int j = 0; j < 8; j++) {
            float v = acc[i][j];
            if (EPI & 1) v += bias[n0 + tc * 8 + j];
            if (EPI & 2) v = fmaxf(v, 0.f);
            if (EPI & 4) v += res[off + j];
            C[off + j] = v;
        }
    }
}

// ---------------------------------------------------------------------------
// Flash attention: grid (S/64, B*H), 256 threads, BQ=64, BKV=32, DK=64.
// Q/K/V in token-major [tok, h*64+dk] layout; output written token-major too.
// ---------------------------------------------------------------------------
__global__ void __launch_bounds__(256) attn_kernel(
    const float* __restrict__ Q, const float* __restrict__ K,
    const float* __restrict__ V, float* __restrict__ O)
{
    const int BQ = 64, BKV = 32;
    __shared__ float sQ[BQ][DK_ + 1];
    __shared__ float sK[BKV][DK_ + 1];
    __shared__ float sV[BKV][DK_ + 1];
    __shared__ float sP[BQ][BKV + 1];

    int tid = threadIdx.x;
    int ty = tid >> 4;          // 0..15
    int tx = tid & 15;          // 0..15
    int qt = blockIdx.x;        // q tile
    int bh = blockIdx.y;        // b*H + h
    int b  = bh >> 4;           // H_ = 16
    int h  = bh & 15;

    size_t base = ((size_t)b * S_) * D_ + (size_t)h * DK_;

    // load Q tile, pre-scaled by 1/sqrt(DK)
    for (int i = tid; i < BQ * (DK_ / 4); i += 256) {
        int r  = i >> 4;            // /16
        int c4 = (i & 15) * 4;
        float4 v = *(const float4*)(Q + base + (size_t)(qt * BQ + r) * D_ + c4);
        sQ[r][c4 + 0] = v.x * 0.125f;
        sQ[r][c4 + 1] = v.y * 0.125f;
        sQ[r][c4 + 2] = v.z * 0.125f;
        sQ[r][c4 + 3] = v.w * 0.125f;
    }

    float m_i[4], l_i[4], o_acc[4][4];
    #pragma unroll
    for (int i = 0; i < 4; i++) {
        m_i[i] = -INFINITY; l_i[i] = 0.f;
        #pragma unroll
        for (int j = 0; j < 4; j++) o_acc[i][j] = 0.f;
    }

    int r0 = ty * 4;    // rows owned
    int c0 = tx * 2;    // S-cols owned

    for (int kt = 0; kt < S_ / BKV; kt++) {
        __syncthreads();   // previous iteration's smem consumers done (also covers Q load)
        for (int i = tid; i < BKV * (DK_ / 4); i += 256) {
            int r  = i >> 4;
            int c4 = (i & 15) * 4;
            size_t goff = base + (size_t)(kt * BKV + r) * D_ + c4;
            float4 kv = *(const float4*)(K + goff);
            float4 vv = *(const float4*)(V + goff);
            sK[r][c4 + 0] = kv.x; sK[r][c4 + 1] = kv.y;
            sK[r][c4 + 2] = kv.z; sK[r][c4 + 3] = kv.w;
            sV[r][c4 + 0] = vv.x; sV[r][c4 + 1] = vv.y;
            sV[r][c4 + 2] = vv.z; sV[r][c4 + 3] = vv.w;
        }
        __syncthreads();

        // S = Q K^T for this tile: each thread 4 rows x 2 cols
        float s[4][2];
        #pragma unroll
        for (int i = 0; i < 4; i++) { s[i][0] = 0.f; s[i][1] = 0.f; }
        #pragma unroll 8
        for (int d = 0; d < DK_; d++) {
            float q0 = sQ[r0 + 0][d], q1 = sQ[r0 + 1][d];
            float q2 = sQ[r0 + 2][d], q3 = sQ[r0 + 3][d];
            float ka = sK[c0 + 0][d], kb = sK[c0 + 1][d];
            s[0][0] += q0 * ka; s[0][1] += q0 * kb;
            s[1][0] += q1 * ka; s[1][1] += q1 * kb;
            s[2][0] += q2 * ka; s[2][1] += q2 * kb;
            s[3][0] += q3 * ka; s[3][1] += q3 * kb;
        }

        // online softmax per row (reduce over the 16 tx lanes; offsets 1..8 stay in-group)
        float factor[4];
        #pragma unroll
        for (int i = 0; i < 4; i++) {
            float lm = fmaxf(s[i][0], s[i][1]);
            #pragma unroll
            for (int o = 8; o > 0; o >>= 1)
                lm = fmaxf(lm, __shfl_xor_sync(0xffffffffu, lm, o));
            float mn = fmaxf(m_i[i], lm);
            factor[i] = __expf(m_i[i] - mn);
            m_i[i] = mn;
            float p0 = __expf(s[i][0] - mn);
            float p1 = __expf(s[i][1] - mn);
            sP[r0 + i][c0 + 0] = p0;
            sP[r0 + i][c0 + 1] = p1;
            float ls = p0 + p1;
            #pragma unroll
            for (int o = 8; o > 0; o >>= 1)
                ls += __shfl_xor_sync(0xffffffffu, ls, o);
            l_i[i] = l_i[i] * factor[i] + ls;
        }
        #pragma unroll
        for (int i = 0; i < 4; i++)
            #pragma unroll
            for (int j = 0; j < 4; j++) o_acc[i][j] *= factor[i];

        __syncthreads();   // sP fully written

        // O += P @ V : thread owns rows r0..r0+3, dims tx*4..tx*4+3
        #pragma unroll 4
        for (int c = 0; c < BKV; c++) {
            float p0 = sP[r0 + 0][c], p1 = sP[r0 + 1][c];
            float p2 = sP[r0 + 2][c], p3 = sP[r0 + 3][c];
            float v0 = sV[c][tx * 4 + 0], v1 = sV[c][tx * 4 + 1];
            float v2 = sV[c][tx * 4 + 2], v3 = sV[c][tx * 4 + 3];
            o_acc[0][0] += p0 * v0; o_acc[0][1] += p0 * v1; o_acc[0][2] += p0 * v2; o_acc[0][3] += p0 * v3;
            o_acc[1][0] += p1 * v0; o_acc[1][1] += p1 * v1; o_acc[1][2] += p1 * v2; o_acc[1][3] += p1 * v3;
            o_acc[2][0] += p2 * v0; o_acc[2][1] += p2 * v1; o_acc[2][2] += p2 * v2; o_acc[2][3] += p2 * v3;
            o_acc[3][0] += p3 * v0; o_acc[3][1] += p3 * v1; o_acc[3][2] += p3 * v2; o_acc[3][3] += p3 * v3;
        }
    }

    #pragma unroll
    for (int i = 0; i < 4; i++) {
        float inv_l = 1.f / l_i[i];
        size_t off = base + (size_t)(qt * BQ + r0 + i) * D_ + tx * 4;
        #pragma unroll
        for (int j = 0; j < 4; j++)
            O[off + j] = o_acc[i][j] * inv_l;
    }
}

// ---------------------------------------------------------------------------
// Launch
// ---------------------------------------------------------------------------
extern "C" void kernel_launch(void* const* d_in, const int* in_sizes, int n_in,
                              void* d_out, int out_size)
{
    const float* x   = (const float*)d_in[0];
    const float* wq  = (const float*)d_in[1];
    const float* wk  = (const float*)d_in[2];
    const float* wv  = (const float*)d_in[3];
    const float* wo  = (const float*)d_in[4];
    const float* w1  = (const float*)d_in[5];
    const float* b1  = (const float*)d_in[6];
    const float* w2  = (const float*)d_in[7];
    const float* b2  = (const float*)d_in[8];
    const float* g1  = (const float*)d_in[9];
    const float* be1 = (const float*)d_in[10];
    const float* g2  = (const float*)d_in[11];
    const float* be2 = (const float*)d_in[12];
    float* out = (float*)d_out;

    float *h, *q, *k, *v, *at, *x1, *h2, *ff;
    cudaGetSymbolAddress((void**)&h,  g_h);
    cudaGetSymbolAddress((void**)&q,  g_q);
    cudaGetSymbolAddress((void**)&k,  g_k);
    cudaGetSymbolAddress((void**)&v,  g_v);
    cudaGetSymbolAddress((void**)&at, g_at);
    cudaGetSymbolAddress((void**)&x1, g_x1);
    cudaGetSymbolAddress((void**)&h2, g_h2);
    cudaGetSymbolAddress((void**)&ff, g_ff);

    dim3 blk(256);
    dim3 grid_sq(D_ / 128, NTOK / 128);      // [8192 x 1024] tiles
    dim3 grid_ff(DFF_ / 128, NTOK / 128);    // [8192 x 4096] tiles

    // 1) h = LN1(x)
    ln_kernel<<<NTOK, blk>>>(x, g1, be1, h);

    // 2-4) q,k,v projections
    sgemm_kernel<0><<<grid_sq, blk>>>(NTOK, D_, D_, h, wq, nullptr, nullptr, q);
    sgemm_kernel<0><<<grid_sq, blk>>>(NTOK, D_, D_, h, wk, nullptr, nullptr, k);
    sgemm_kernel<0><<<grid_sq, blk>>>(NTOK, D_, D_, h, wv, nullptr, nullptr, v);

    // 5) attention (flash, per (b,h))
    attn_kernel<<<dim3(S_ / 64, B_ * H_), blk>>>(q, k, v, at);

    // 6) x1 = x + attn @ wo
    sgemm_kernel<4><<<grid_sq, blk>>>(NTOK, D_, D_, at, wo, nullptr, x, x1);

    // 7) h2 = LN2(x1)
    ln_kernel<<<NTOK, blk>>>(x1, g2, be2, h2);

    // 8) ff = relu(h2 @ w1 + b1)
    sgemm_kernel<3><<<grid_ff, blk>>>(NTOK, DFF_, D_, h2, w1, b1, nullptr, ff);

    // 9) out = x1 + ff @ w2 + b2
    sgemm_kernel<5><<<grid_sq, blk>>>(NTOK, D_, DFF_, ff, w2, b2, x1, out);
}

// round 9
// speedup vs baseline: 1.7044x; 1.7044x over previous
#include <cuda_runtime.h>
#include <math.h>
#include <stdint.h>

// Problem constants
#define B_   4
#define S_   2048
#define D_   1024
#define H_   16
#define DK_  64
#define DFF_ 4096
#define NTOK (B_*S_)     // 8192 tokens
#define EPS_ 1e-5f

// ---------------------------------------------------------------------------
// Scratch (device globals: allocation-free, allowed by harness rules)
// ---------------------------------------------------------------------------
__device__ float g_h [(size_t)NTOK*D_];   // LN1 output
__device__ float g_q [(size_t)NTOK*D_];
__device__ float g_k [(size_t)NTOK*D_];
__device__ float g_v [(size_t)NTOK*D_];
__device__ float g_at[(size_t)NTOK*D_];
__device__ float g_x1[(size_t)NTOK*D_];
__device__ float g_h2[(size_t)NTOK*D_];
__device__ float g_ff[(size_t)NTOK*DFF_];

// ---------------------------------------------------------------------------
// LayerNorm: one block per row (D=1024, 256 threads, 1 float4/thread)
// ---------------------------------------------------------------------------
__global__ void __launch_bounds__(256) ln_kernel(
    const float* __restrict__ x, const float* __restrict__ g,
    const float* __restrict__ b, float* __restrict__ out)
{
    int row = blockIdx.x;
    int tid = threadIdx.x;
    const float4* xr = (const float4*)(x + (size_t)row * D_);
    float4 xv = xr[tid];

    float s  = xv.x + xv.y + xv.z + xv.w;
    float ss = xv.x*xv.x + xv.y*xv.y + xv.z*xv.z + xv.w*xv.w;

    #pragma unroll
    for (int o = 16; o > 0; o >>= 1) {
        s  += __shfl_xor_sync(0xffffffffu, s,  o);
        ss += __shfl_xor_sync(0xffffffffu, ss, o);
    }
    __shared__ float sh_s[8], sh_ss[8];
    __shared__ float mu_sh, rs_sh;
    if ((tid & 31) == 0) { sh_s[tid >> 5] = s; sh_ss[tid >> 5] = ss; }
    __syncthreads();
    if (tid == 0) {
        float S = 0.f, SS = 0.f;
        #pragma unroll
        for (int i = 0; i < 8; i++) { S += sh_s[i]; SS += sh_ss[i]; }
        float mu  = S / (float)D_;
        float var = SS / (float)D_ - mu * mu;
        mu_sh = mu;
        rs_sh = rsqrtf(var + EPS_);
    }
    __syncthreads();
    float mu = mu_sh, rs = rs_sh;

    const float4* gr = (const float4*)g;
    const float4* br = (const float4*)b;
    float4 gv = gr[tid], bv = br[tid];
    float4 o;
    o.x = (xv.x - mu) * rs * gv.x + bv.x;
    o.y = (xv.y - mu) * rs * gv.y + bv.y;
    o.z = (xv.z - mu) * rs * gv.z + bv.z;
    o.w = (xv.w - mu) * rs * gv.w + bv.w;
    ((float4*)(out + (size_t)row * D_))[tid] = o;
}

// ---------------------------------------------------------------------------
// TF32 tensor-core GEMM: C[M,N] = epi(A[M,K] @ B[K,N])
// BM=BN=128, BK=16, 256 threads (8 warps, 2x4), warp tile 64x32,
// mma.sync.m16n8k8.tf32, double-buffered smem, cvt.rna on smem fill.
// EPI bit0 = +bias[n], bit1 = relu, bit2 = +res[m,n]
// Requires M%128==0, N%128==0, K%16==0.
// ---------------------------------------------------------------------------
#define PADA 132
#define PADB 132

__device__ __forceinline__ uint32_t f2tf32(float f) {
    uint32_t u;
    asm("cvt.rna.tf32.f32 %0, %1;" : "=r"(u) : "f"(f));
    return u;
}

__device__ __forceinline__ void mma_tf32(float* c, const uint32_t* a, const uint32_t* b) {
    asm volatile(
        "mma.sync.aligned.m16n8k8.row.col.f32.tf32.tf32.f32 "
        "{%0,%1,%2,%3}, {%4,%5,%6,%7}, {%8,%9}, {%0,%1,%2,%3};\n"
        : "+f"(c[0]), "+f"(c[1]), "+f"(c[2]), "+f"(c[3])
        : "r"(a[0]), "r"(a[1]), "r"(a[2]), "r"(a[3]),
          "r"(b[0]), "r"(b[1]));
}

template<int EPI>
__global__ void __launch_bounds__(256, 2) tf32gemm_kernel(
    int M, int N, int K,
    const float* __restrict__ A, const float* __restrict__ Bm,
    const float* __restrict__ bias, const float* __restrict__ res,
    float* __restrict__ C)
{
    __shared__ uint32_t As[2][16][PADA];
    __shared__ uint32_t Bs[2][16][PADB];

    int tid  = threadIdx.x;
    int lane = tid & 31;
    int warp = tid >> 5;
    int wm = (warp >> 2) * 64;   // warp m-offset within block tile
    int wn = (warp & 3) * 32;    // warp n-offset
    int m0 = blockIdx.y * 128;
    int n0 = blockIdx.x * 128;
    int tg = lane & 3;           // thread-in-group (k / col pairs)
    int gp = lane >> 2;          // group id (row / col)

    const float* Abase = A + (size_t)m0 * K;
    const float* Bbase = Bm + n0;

    float acc[4][4][4];
    #pragma unroll
    for (int mt = 0; mt < 4; mt++)
        #pragma unroll
        for (int nt = 0; nt < 4; nt++)
            #pragma unroll
            for (int c = 0; c < 4; c++) acc[mt][nt][c] = 0.f;

    float4 aldr[2], bldr[2];

    // ---- loaders ----
    // A tile: 128m x 16k. idx = tid + 256*i : m = idx>>2, kq = idx&3 (float4 at k=4*kq)
    // B tile: 16k x 128n. idx = tid + 256*i : k = idx>>5, n4 = idx&31
    #define LD_A(k0) { _Pragma("unroll") for (int i = 0; i < 2; i++) { \
        int idx = tid + i*256; int m = idx >> 2; int kq = idx & 3;     \
        aldr[i] = *(const float4*)(Abase + (size_t)m * K + (k0) + kq*4); } }
    #define LD_B(k0) { _Pragma("unroll") for (int i = 0; i < 2; i++) { \
        int idx = tid + i*256; int k = idx >> 5; int n4 = idx & 31;    \
        bldr[i] = *(const float4*)(Bbase + (size_t)((k0) + k) * N + n4*4); } }
    #define ST_AB(sg) { _Pragma("unroll") for (int i = 0; i < 2; i++) { \
        int idx = tid + i*256; int m = idx >> 2; int kq = idx & 3;      \
        As[sg][kq*4+0][m] = f2tf32(aldr[i].x);                          \
        As[sg][kq*4+1][m] = f2tf32(aldr[i].y);                          \
        As[sg][kq*4+2][m] = f2tf32(aldr[i].z);                          \
        As[sg][kq*4+3][m] = f2tf32(aldr[i].w);                          \
        int k = idx >> 5; int n4 = idx & 31;                            \
        uint32_t* p = &Bs[sg][k][n4*4];                                 \
        p[0] = f2tf32(bldr[i].x); p[1] = f2tf32(bldr[i].y);             \
        p[2] = f2tf32(bldr[i].z); p[3] = f2tf32(bldr[i].w); } }

    LD_A(0); LD_B(0);
    ST_AB(0);
    __syncthreads();

    int s = 0;
    for (int k0 = 0; k0 < K; k0 += 16) {
        bool more = (k0 + 16) < K;
        if (more) { LD_A(k0 + 16); LD_B(k0 + 16); }

        #pragma unroll
        for (int kk = 0; kk < 16; kk += 8) {
            uint32_t af[4][4], bf[4][2];
            int kb = kk + tg;
            #pragma unroll
            for (int mt = 0; mt < 4; mt++) {
                int rb = wm + mt*16 + gp;
                af[mt][0] = As[s][kb    ][rb];
                af[mt][1] = As[s][kb    ][rb + 8];
                af[mt][2] = As[s][kb + 4][rb];
                af[mt][3] = As[s][kb + 4][rb + 8];
            }
            #pragma unroll
            for (int nt = 0; nt < 4; nt++) {
                int cb = wn + nt*8 + gp;
                bf[nt][0] = Bs[s][kb    ][cb];
                bf[nt][1] = Bs[s][kb + 4][cb];
            }
            #pragma unroll
            for (int mt = 0; mt < 4; mt++)
                #pragma unroll
                for (int nt = 0; nt < 4; nt++)
                    mma_tf32(acc[mt][nt], af[mt], bf[nt]);
        }

        if (more) ST_AB(s ^ 1);
        __syncthreads();
        s ^= 1;
    }

    // ---- epilogue ----
    #pragma unroll
    for (int mt = 0; mt < 4; mt++) {
        int row0 = m0 + wm + mt*16 + gp;
        #pragma unroll
        for (int nt = 0; nt < 4; nt++) {
            int col = n0 + wn + nt*8 + tg*2;
            #pragma unroll
            for (int half = 0; half < 2; half++) {
                int r = row0 + half*8;
                size_t off = (size_t)r * N + col;
                float v0 = acc[mt][nt][half*2 + 0];
                float v1 = acc[mt][nt][half*2 + 1];
                if (EPI & 1) { v0 += bias[col]; v1 += bias[col + 1]; }
                if (EPI & 2) { v0 = fmaxf(v0, 0.f); v1 = fmaxf(v1, 0.f); }
                if (EPI & 4) { float2 rv = *(const float2*)(res + off);
                               v0 += rv.x; v1 += rv.y; }
                float2 ov; ov.x = v0; ov.y = v1;
                *(float2*)(C + off) = ov;
            }
        }
    }
    #undef LD_A
    #undef LD_B
    #undef ST_AB
}

// ---------------------------------------------------------------------------
// Flash attention: grid (S/64, B*H), 256 threads, BQ=64, BKV=32, DK=64.
// (unchanged this round; fp32)
// ---------------------------------------------------------------------------
__global__ void __launch_bounds__(256) attn_kernel(
    const float* __restrict__ Q, const float* __restrict__ K,
    const float* __restrict__ V, float* __restrict__ O)
{
    const int BQ = 64, BKV = 32;
    __shared__ float sQ[BQ][DK_ + 1];
    __shared__ float sK[BKV][DK_ + 1];
    __shared__ float sV[BKV][DK_ + 1];
    __shared__ float sP[BQ][BKV + 1];

    int tid = threadIdx.x;
    int ty = tid >> 4;
    int tx = tid & 15;
    int qt = blockIdx.x;
    int bh = blockIdx.y;
    int b  = bh >> 4;
    int h  = bh & 15;

    size_t base = ((size_t)b * S_) * D_ + (size_t)h * DK_;

    for (int i = tid; i < BQ * (DK_ / 4); i += 256) {
        int r  = i >> 4;
        int c4 = (i & 15) * 4;
        float4 v = *(const float4*)(Q + base + (size_t)(qt * BQ + r) * D_ + c4);
        sQ[r][c4 + 0] = v.x * 0.125f;
        sQ[r][c4 + 1] = v.y * 0.125f;
        sQ[r][c4 + 2] = v.z * 0.125f;
        sQ[r][c4 + 3] = v.w * 0.125f;
    }

    float m_i[4], l_i[4], o_acc[4][4];
    #pragma unroll
    for (int i = 0; i < 4; i++) {
        m_i[i] = -INFINITY; l_i[i] = 0.f;
        #pragma unroll
        for (int j = 0; j < 4; j++) o_acc[i][j] = 0.f;
    }

    int r0 = ty * 4;
    int c0 = tx * 2;

    for (int kt = 0; kt < S_ / BKV; kt++) {
        __syncthreads();
        for (int i = tid; i < BKV * (DK_ / 4); i += 256) {
            int r  = i >> 4;
            int c4 = (i & 15) * 4;
            size_t goff = base + (size_t)(kt * BKV + r) * D_ + c4;
            float4 kv = *(const float4*)(K + goff);
            float4 vv = *(const float4*)(V + goff);
            sK[r][c4 + 0] = kv.x; sK[r][c4 + 1] = kv.y;
            sK[r][c4 + 2] = kv.z; sK[r][c4 + 3] = kv.w;
            sV[r][c4 + 0] = vv.x; sV[r][c4 + 1] = vv.y;
            sV[r][c4 + 2] = vv.z; sV[r][c4 + 3] = vv.w;
        }
        __syncthreads();

        float s[4][2];
        #pragma unroll
        for (int i = 0; i < 4; i++) { s[i][0] = 0.f; s[i][1] = 0.f; }
        #pragma unroll 8
        for (int d = 0; d < DK_; d++) {
            float q0 = sQ[r0 + 0][d], q1 = sQ[r0 + 1][d];
            float q2 = sQ[r0 + 2][d], q3 = sQ[r0 + 3][d];
            float ka = sK[c0 + 0][d], kb = sK[c0 + 1][d];
            s[0][0] += q0 * ka; s[0][1] += q0 * kb;
            s[1][0] += q1 * ka; s[1][1] += q1 * kb;
            s[2][0] += q2 * ka; s[2][1] += q2 * kb;
            s[3][0] += q3 * ka; s[3][1] += q3 * kb;
        }

        float factor[4];
        #pragma unroll
        for (int i = 0; i < 4; i++) {
            float lm = fmaxf(s[i][0], s[i][1]);
            #pragma unroll
            for (int o = 8; o > 0; o >>= 1)
                lm = fmaxf(lm, __shfl_xor_sync(0xffffffffu, lm, o));
            float mn = fmaxf(m_i[i], lm);
            factor[i] = __expf(m_i[i] - mn);
            m_i[i] = mn;
            float p0 = __expf(s[i][0] - mn);
            float p1 = __expf(s[i][1] - mn);
            sP[r0 + i][c0 + 0] = p0;
            sP[r0 + i][c0 + 1] = p1;
            float ls = p0 + p1;
            #pragma unroll
            for (int o = 8; o > 0; o >>= 1)
                ls += __shfl_xor_sync(0xffffffffu, ls, o);
            l_i[i] = l_i[i] * factor[i] + ls;
        }
        #pragma unroll
        for (int i = 0; i < 4; i++)
            #pragma unroll
            for (int j = 0; j < 4; j++) o_acc[i][j] *= factor[i];

        __syncthreads();

        #pragma unroll 4
        for (int c = 0; c < BKV; c++) {
            float p0 = sP[r0 + 0][c], p1 = sP[r0 + 1][c];
            float p2 = sP[r0 + 2][c], p3 = sP[r0 + 3][c];
            float v0 = sV[c][tx * 4 + 0], v1 = sV[c][tx * 4 + 1];
            float v2 = sV[c][tx * 4 + 2], v3 = sV[c][tx * 4 + 3];
            o_acc[0][0] += p0 * v0; o_acc[0][1] += p0 * v1; o_acc[0][2] += p0 * v2; o_acc[0][3] += p0 * v3;
            o_acc[1][0] += p1 * v0; o_acc[1][1] += p1 * v1; o_acc[1][2] += p1 * v2; o_acc[1][3] += p1 * v3;
            o_acc[2][0] += p2 * v0; o_acc[2][1] += p2 * v1; o_acc[2][2] += p2 * v2; o_acc[2][3] += p2 * v3;
            o_acc[3][0] += p3 * v0; o_acc[3][1] += p3 * v1; o_acc[3][2] += p3 * v2; o_acc[3][3] += p3 * v3;
        }
    }

    #pragma unroll
    for (int i = 0; i < 4; i++) {
        float inv_l = 1.f / l_i[i];
        size_t off = base + (size_t)(qt * BQ + r0 + i) * D_ + tx * 4;
        #pragma unroll
        for (int j = 0; j < 4; j++)
            O[off + j] = o_acc[i][j] * inv_l;
    }
}

// ---------------------------------------------------------------------------
// Launch
// ---------------------------------------------------------------------------
extern "C" void kernel_launch(void* const* d_in, const int* in_sizes, int n_in,
                              void* d_out, int out_size)
{
    const float* x   = (const float*)d_in[0];
    const float* wq  = (const float*)d_in[1];
    const float* wk  = (const float*)d_in[2];
    const float* wv  = (const float*)d_in[3];
    const float* wo  = (const float*)d_in[4];
    const float* w1  = (const float*)d_in[5];
    const float* b1  = (const float*)d_in[6];
    const float* w2  = (const float*)d_in[7];
    const float* b2  = (const float*)d_in[8];
    const float* g1  = (const float*)d_in[9];
    const float* be1 = (const float*)d_in[10];
    const float* g2  = (const float*)d_in[11];
    const float* be2 = (const float*)d_in[12];
    float* out = (float*)d_out;

    float *h, *q, *k, *v, *at, *x1, *h2, *ff;
    cudaGetSymbolAddress((void**)&h,  g_h);
    cudaGetSymbolAddress((void**)&q,  g_q);
    cudaGetSymbolAddress((void**)&k,  g_k);
    cudaGetSymbolAddress((void**)&v,  g_v);
    cudaGetSymbolAddress((void**)&at, g_at);
    cudaGetSymbolAddress((void**)&x1, g_x1);
    cudaGetSymbolAddress((void**)&h2, g_h2);
    cudaGetSymbolAddress((void**)&ff, g_ff);

    dim3 blk(256);
    dim3 grid_sq(D_ / 128, NTOK / 128);      // [8192 x 1024] tiles
    dim3 grid_ff(DFF_ / 128, NTOK / 128);    // [8192 x 4096] tiles

    // 1) h = LN1(x)
    ln_kernel<<<NTOK, blk>>>(x, g1, be1, h);

    // 2-4) q,k,v projections (tf32 tensor cores)
    tf32gemm_kernel<0><<<grid_sq, blk>>>(NTOK, D_, D_, h, wq, nullptr, nullptr, q);
    tf32gemm_kernel<0><<<grid_sq, blk>>>(NTOK, D_, D_, h, wk, nullptr, nullptr, k);
    tf32gemm_kernel<0><<<grid_sq, blk>>>(NTOK, D_, D_, h, wv, nullptr, nullptr, v);

    // 5) attention (flash, per (b,h))
    attn_kernel<<<dim3(S_ / 64, B_ * H_), blk>>>(q, k, v, at);

    // 6) x1 = x + attn @ wo
    tf32gemm_kernel<4><<<grid_sq, blk>>>(NTOK, D_, D_, at, wo, nullptr, x, x1);

    // 7) h2 = LN2(x1)
    ln_kernel<<<NTOK, blk>>>(x1, g2, be2, h2);

    // 8) ff = relu(h2 @ w1 + b1)
    tf32gemm_kernel<3><<<grid_ff, blk>>>(NTOK, DFF_, D_, h2, w1, b1, nullptr, ff);

    // 9) out = x1 + ff @ w2 + b2
    tf32gemm_kernel<5><<<grid_sq, blk>>>(NTOK, D_, DFF_, ff, w2, b2, x1, out);
}

// round 11
// speedup vs baseline: 2.7148x; 1.5929x over previous
#include <cuda_runtime.h>
#include <math.h>
#include <stdint.h>

// Problem constants
#define B_   4
#define S_   2048
#define D_   1024
#define H_   16
#define DK_  64
#define DFF_ 4096
#define NTOK (B_*S_)     // 8192 tokens
#define EPS_ 1e-5f

// ---------------------------------------------------------------------------
// Scratch (device globals: allocation-free, allowed by harness rules)
// ---------------------------------------------------------------------------
__device__ float g_h [(size_t)NTOK*D_];   // LN1 output
__device__ float g_q [(size_t)NTOK*D_];
__device__ float g_k [(size_t)NTOK*D_];
__device__ float g_v [(size_t)NTOK*D_];
__device__ float g_at[(size_t)NTOK*D_];
__device__ float g_x1[(size_t)NTOK*D_];
__device__ float g_h2[(size_t)NTOK*D_];
__device__ float g_ff[(size_t)NTOK*DFF_];

// ---------------------------------------------------------------------------
// Common TF32 helpers
// ---------------------------------------------------------------------------
__device__ __forceinline__ uint32_t f2tf32(float f) {
    uint32_t u;
    asm("cvt.rna.tf32.f32 %0, %1;" : "=r"(u) : "f"(f));
    return u;
}

__device__ __forceinline__ void mma_tf32(float* c, const uint32_t* a, const uint32_t* b) {
    asm volatile(
        "mma.sync.aligned.m16n8k8.row.col.f32.tf32.tf32.f32 "
        "{%0,%1,%2,%3}, {%4,%5,%6,%7}, {%8,%9}, {%0,%1,%2,%3};\n"
        : "+f"(c[0]), "+f"(c[1]), "+f"(c[2]), "+f"(c[3])
        : "r"(a[0]), "r"(a[1]), "r"(a[2]), "r"(a[3]),
          "r"(b[0]), "r"(b[1]));
}

// ---------------------------------------------------------------------------
// LayerNorm: one block per row (D=1024, 256 threads, 1 float4/thread)
// ---------------------------------------------------------------------------
__global__ void __launch_bounds__(256) ln_kernel(
    const float* __restrict__ x, const float* __restrict__ g,
    const float* __restrict__ b, float* __restrict__ out)
{
    int row = blockIdx.x;
    int tid = threadIdx.x;
    const float4* xr = (const float4*)(x + (size_t)row * D_);
    float4 xv = xr[tid];

    float s  = xv.x + xv.y + xv.z + xv.w;
    float ss = xv.x*xv.x + xv.y*xv.y + xv.z*xv.z + xv.w*xv.w;

    #pragma unroll
    for (int o = 16; o > 0; o >>= 1) {
        s  += __shfl_xor_sync(0xffffffffu, s,  o);
        ss += __shfl_xor_sync(0xffffffffu, ss, o);
    }
    __shared__ float sh_s[8], sh_ss[8];
    __shared__ float mu_sh, rs_sh;
    if ((tid & 31) == 0) { sh_s[tid >> 5] = s; sh_ss[tid >> 5] = ss; }
    __syncthreads();
    if (tid == 0) {
        float S = 0.f, SS = 0.f;
        #pragma unroll
        for (int i = 0; i < 8; i++) { S += sh_s[i]; SS += sh_ss[i]; }
        float mu  = S / (float)D_;
        float var = SS / (float)D_ - mu * mu;
        mu_sh = mu;
        rs_sh = rsqrtf(var + EPS_);
    }
    __syncthreads();
    float mu = mu_sh, rs = rs_sh;

    const float4* gr = (const float4*)g;
    const float4* br = (const float4*)b;
    float4 gv = gr[tid], bv = br[tid];
    float4 o;
    o.x = (xv.x - mu) * rs * gv.x + bv.x;
    o.y = (xv.y - mu) * rs * gv.y + bv.y;
    o.z = (xv.z - mu) * rs * gv.z + bv.z;
    o.w = (xv.w - mu) * rs * gv.w + bv.w;
    ((float4*)(out + (size_t)row * D_))[tid] = o;
}

// ---------------------------------------------------------------------------
// TF32 tensor-core GEMM: C[M,N] = epi(A[M,K] @ B[K,N])
// BM=BN=128, BK=16, 256 threads (8 warps, 2x4), warp tile 64x32,
// mma.sync.m16n8k8.tf32, double-buffered smem, cvt.rna on smem fill.
// EPI bit0 = +bias[n], bit1 = relu, bit2 = +res[m,n]
// ---------------------------------------------------------------------------
#define PADA 132
#define PADB 132

template<int EPI>
__global__ void __launch_bounds__(256, 2) tf32gemm_kernel(
    int M, int N, int K,
    const float* __restrict__ A, const float* __restrict__ Bm,
    const float* __restrict__ bias, const float* __restrict__ res,
    float* __restrict__ C)
{
    __shared__ uint32_t As[2][16][PADA];
    __shared__ uint32_t Bs[2][16][PADB];

    int tid  = threadIdx.x;
    int lane = tid & 31;
    int warp = tid >> 5;
    int wm = (warp >> 2) * 64;
    int wn = (warp & 3) * 32;
    int m0 = blockIdx.y * 128;
    int n0 = blockIdx.x * 128;
    int tg = lane & 3;
    int gp = lane >> 2;

    const float* Abase = A + (size_t)m0 * K;
    const float* Bbase = Bm + n0;

    float acc[4][4][4];
    #pragma unroll
    for (int mt = 0; mt < 4; mt++)
        #pragma unroll
        for (int nt = 0; nt < 4; nt++)
            #pragma unroll
            for (int c = 0; c < 4; c++) acc[mt][nt][c] = 0.f;

    float4 aldr[2], bldr[2];

    #define LD_A(k0) { _Pragma("unroll") for (int i = 0; i < 2; i++) { \
        int idx = tid + i*256; int m = idx >> 2; int kq = idx & 3;     \
        aldr[i] = *(const float4*)(Abase + (size_t)m * K + (k0) + kq*4); } }
    #define LD_B(k0) { _Pragma("unroll") for (int i = 0; i < 2; i++) { \
        int idx = tid + i*256; int k = idx >> 5; int n4 = idx & 31;    \
        bldr[i] = *(const float4*)(Bbase + (size_t)((k0) + k) * N + n4*4); } }
    #define ST_AB(sg) { _Pragma("unroll") for (int i = 0; i < 2; i++) { \
        int idx = tid + i*256; int m = idx >> 2; int kq = idx & 3;      \
        As[sg][kq*4+0][m] = f2tf32(aldr[i].x);                          \
        As[sg][kq*4+1][m] = f2tf32(aldr[i].y);                          \
        As[sg][kq*4+2][m] = f2tf32(aldr[i].z);                          \
        As[sg][kq*4+3][m] = f2tf32(aldr[i].w);                          \
        int k = idx >> 5; int n4 = idx & 31;                            \
        uint32_t* p = &Bs[sg][k][n4*4];                                 \
        p[0] = f2tf32(bldr[i].x); p[1] = f2tf32(bldr[i].y);             \
        p[2] = f2tf32(bldr[i].z); p[3] = f2tf32(bldr[i].w); } }

    LD_A(0); LD_B(0);
    ST_AB(0);
    __syncthreads();

    int s = 0;
    for (int k0 = 0; k0 < K; k0 += 16) {
        bool more = (k0 + 16) < K;
        if (more) { LD_A(k0 + 16); LD_B(k0 + 16); }

        #pragma unroll
        for (int kk = 0; kk < 16; kk += 8) {
            uint32_t af[4][4], bf[4][2];
            int kb = kk + tg;
            #pragma unroll
            for (int mt = 0; mt < 4; mt++) {
                int rb = wm + mt*16 + gp;
                af[mt][0] = As[s][kb    ][rb];
                af[mt][1] = As[s][kb    ][rb + 8];
                af[mt][2] = As[s][kb + 4][rb];
                af[mt][3] = As[s][kb + 4][rb + 8];
            }
            #pragma unroll
            for (int nt = 0; nt < 4; nt++) {
                int cb = wn + nt*8 + gp;
                bf[nt][0] = Bs[s][kb    ][cb];
                bf[nt][1] = Bs[s][kb + 4][cb];
            }
            #pragma unroll
            for (int mt = 0; mt < 4; mt++)
                #pragma unroll
                for (int nt = 0; nt < 4; nt++)
                    mma_tf32(acc[mt][nt], af[mt], bf[nt]);
        }

        if (more) ST_AB(s ^ 1);
        __syncthreads();
        s ^= 1;
    }

    #pragma unroll
    for (int mt = 0; mt < 4; mt++) {
        int row0 = m0 + wm + mt*16 + gp;
        #pragma unroll
        for (int nt = 0; nt < 4; nt++) {
            int col = n0 + wn + nt*8 + tg*2;
            #pragma unroll
            for (int half = 0; half < 2; half++) {
                int r = row0 + half*8;
                size_t off = (size_t)r * N + col;
                float v0 = acc[mt][nt][half*2 + 0];
                float v1 = acc[mt][nt][half*2 + 1];
                if (EPI & 1) { v0 += bias[col]; v1 += bias[col + 1]; }
                if (EPI & 2) { v0 = fmaxf(v0, 0.f); v1 = fmaxf(v1, 0.f); }
                if (EPI & 4) { float2 rv = *(const float2*)(res + off);
                               v0 += rv.x; v1 += rv.y; }
                float2 ov; ov.x = v0; ov.y = v1;
                *(float2*)(C + off) = ov;
            }
        }
    }
    #undef LD_A
    #undef LD_B
    #undef ST_AB
}

// ---------------------------------------------------------------------------
// TF32 tensor-core flash attention.
// grid (S/128, B*H), 256 threads (8 warps), BQ=128 (16 rows/warp), BKV=64.
// S = Q@K^T and O += P@V both via mma.m16n8k8.tf32.
// Smem (dynamic, u32):
//   sQ [128][68]  (tf32, pre-scaled 1/8)
//   sK [64][68]   ([key][dk])
//   sV [64][72]   ([key][dv], pad 72 -> conflict-free B-frag reads)
//   sP [128][68]  (P tf32 staging: C-frag -> A-frag reshape)
// ---------------------------------------------------------------------------
#define SQS 68
#define SKS 68
#define SVS 72
#define SPS 68
#define OFF_K 8704            // 128*68
#define OFF_V 13056           // + 64*68
#define OFF_P 17664           // + 64*72
#define ATTN_SMEM_U32 26368   // + 128*68
#define ATTN_SMEM_BYTES (ATTN_SMEM_U32 * 4)

__global__ void __launch_bounds__(256, 2) attn_tc_kernel(
    const float* __restrict__ Q, const float* __restrict__ K,
    const float* __restrict__ V, float* __restrict__ O)
{
    extern __shared__ uint32_t smem_u[];
    uint32_t* sQ = smem_u;
    uint32_t* sK = smem_u + OFF_K;
    uint32_t* sV = smem_u + OFF_V;
    uint32_t* sP = smem_u + OFF_P;

    int tid  = threadIdx.x;
    int warp = tid >> 5;
    int lane = tid & 31;
    int gp = lane >> 2;        // fragment row group
    int tg = lane & 3;         // fragment thread-in-group
    int mw = warp * 16;        // warp's query-row offset in tile

    int qt = blockIdx.x;
    int bh = blockIdx.y;
    int b  = bh >> 4;
    int h  = bh & 15;
    size_t base = ((size_t)b * S_) * D_ + (size_t)h * DK_;

    // --- load Q tile (128 x 64), scale by 1/sqrt(64), convert to tf32 ---
    for (int i = tid; i < 128 * 16; i += 256) {
        int r = i >> 4, c4 = (i & 15) * 4;
        float4 v = *(const float4*)(Q + base + (size_t)(qt * 128 + r) * D_ + c4);
        uint32_t q4[4];
        q4[0] = f2tf32(v.x * 0.125f); q4[1] = f2tf32(v.y * 0.125f);
        q4[2] = f2tf32(v.z * 0.125f); q4[3] = f2tf32(v.w * 0.125f);
        *(uint4*)(sQ + r * SQS + c4) = *(uint4*)q4;
    }

    float oacc[8][4];
    #pragma unroll
    for (int n = 0; n < 8; n++)
        #pragma unroll
        for (int c = 0; c < 4; c++) oacc[n][c] = 0.f;
    float m_lo = -INFINITY, m_hi = -INFINITY;
    float l_lo = 0.f, l_hi = 0.f;

    for (int kt = 0; kt < S_ / 64; kt++) {
        // --- load K,V tile (64 x 64 each) ---
        for (int i = tid; i < 64 * 16; i += 256) {
            int r = i >> 4, c4 = (i & 15) * 4;
            size_t goff = base + (size_t)(kt * 64 + r) * D_ + c4;
            float4 kv = *(const float4*)(K + goff);
            float4 vv = *(const float4*)(V + goff);
            uint32_t k4[4], v4[4];
            k4[0] = f2tf32(kv.x); k4[1] = f2tf32(kv.y);
            k4[2] = f2tf32(kv.z); k4[3] = f2tf32(kv.w);
            v4[0] = f2tf32(vv.x); v4[1] = f2tf32(vv.y);
            v4[2] = f2tf32(vv.z); v4[3] = f2tf32(vv.w);
            *(uint4*)(sK + r * SKS + c4) = *(uint4*)k4;
            *(uint4*)(sV + r * SVS + c4) = *(uint4*)v4;
        }
        __syncthreads();   // K/V (and first-iter Q) visible

        // --- S = Q K^T : warp computes 16 x 64 scores ---
        float sacc[8][4];
        #pragma unroll
        for (int n = 0; n < 8; n++)
            #pragma unroll
            for (int c = 0; c < 4; c++) sacc[n][c] = 0.f;

        #pragma unroll
        for (int k = 0; k < 8; k++) {
            uint32_t aq[4];
            const uint32_t* qr = sQ + (mw + gp) * SQS + k * 8 + tg;
            aq[0] = qr[0];
            aq[1] = qr[8 * SQS];
            aq[2] = qr[4];
            aq[3] = qr[8 * SQS + 4];
            #pragma unroll
            for (int n = 0; n < 8; n++) {
                uint32_t bk[2];
                const uint32_t* kr = sK + (n * 8 + gp) * SKS + k * 8 + tg;
                bk[0] = kr[0];
                bk[1] = kr[4];
                mma_tf32(sacc[n], aq, bk);
            }
        }

        // --- online softmax on fragments (rows gp, gp+8; quad-reduce over tg) ---
        float mx_lo = -INFINITY, mx_hi = -INFINITY;
        #pragma unroll
        for (int n = 0; n < 8; n++) {
            mx_lo = fmaxf(mx_lo, fmaxf(sacc[n][0], sacc[n][1]));
            mx_hi = fmaxf(mx_hi, fmaxf(sacc[n][2], sacc[n][3]));
        }
        mx_lo = fmaxf(mx_lo, __shfl_xor_sync(0xffffffffu, mx_lo, 1));
        mx_lo = fmaxf(mx_lo, __shfl_xor_sync(0xffffffffu, mx_lo, 2));
        mx_hi = fmaxf(mx_hi, __shfl_xor_sync(0xffffffffu, mx_hi, 1));
        mx_hi = fmaxf(mx_hi, __shfl_xor_sync(0xffffffffu, mx_hi, 2));

        float mn_lo = fmaxf(m_lo, mx_lo);
        float mn_hi = fmaxf(m_hi, mx_hi);
        float f_lo = __expf(m_lo - mn_lo);
        float f_hi = __expf(m_hi - mn_hi);
        m_lo = mn_lo; m_hi = mn_hi;

        float s_lo = 0.f, s_hi = 0.f;
        uint32_t* plo_base = sP + (mw + gp) * SPS + tg * 2;
        #pragma unroll
        for (int n = 0; n < 8; n++) {
            float p0 = __expf(sacc[n][0] - mn_lo);
            float p1 = __expf(sacc[n][1] - mn_lo);
            float p2 = __expf(sacc[n][2] - mn_hi);
            float p3 = __expf(sacc[n][3] - mn_hi);
            s_lo += p0 + p1;
            s_hi += p2 + p3;
            uint32_t* plo = plo_base + n * 8;
            plo[0] = f2tf32(p0); plo[1] = f2tf32(p1);
            plo[8 * SPS] = f2tf32(p2); plo[8 * SPS + 1] = f2tf32(p3);
        }
        s_lo += __shfl_xor_sync(0xffffffffu, s_lo, 1);
        s_lo += __shfl_xor_sync(0xffffffffu, s_lo, 2);
        s_hi += __shfl_xor_sync(0xffffffffu, s_hi, 1);
        s_hi += __shfl_xor_sync(0xffffffffu, s_hi, 2);
        l_lo = l_lo * f_lo + s_lo;
        l_hi = l_hi * f_hi + s_hi;

        #pragma unroll
        for (int n = 0; n < 8; n++) {
            oacc[n][0] *= f_lo; oacc[n][1] *= f_lo;
            oacc[n][2] *= f_hi; oacc[n][3] *= f_hi;
        }

        __syncwarp();   // sP written (warp-local) before A-frag re-read

        // --- O += P @ V ---
        #pragma unroll
        for (int k = 0; k < 8; k++) {
            uint32_t ap[4];
            const uint32_t* pr = sP + (mw + gp) * SPS + k * 8 + tg;
            ap[0] = pr[0];
            ap[1] = pr[8 * SPS];
            ap[2] = pr[4];
            ap[3] = pr[8 * SPS + 4];
            #pragma unroll
            for (int n = 0; n < 8; n++) {
                uint32_t bv[2];
                const uint32_t* vr = sV + (k * 8 + tg) * SVS + n * 8 + gp;
                bv[0] = vr[0];
                bv[1] = vr[4 * SVS];
                mma_tf32(oacc[n], ap, bv);
            }
        }
        __syncthreads();   // protect sK/sV before next tile overwrites
    }

    // --- epilogue: normalize and store (token-major) ---
    float inv_lo = 1.f / l_lo;
    float inv_hi = 1.f / l_hi;
    int row_lo = qt * 128 + mw + gp;
    #pragma unroll
    for (int n = 0; n < 8; n++) {
        size_t off_lo = base + (size_t)row_lo * D_ + n * 8 + tg * 2;
        float2 o1; o1.x = oacc[n][0] * inv_lo; o1.y = oacc[n][1] * inv_lo;
        *(float2*)(O + off_lo) = o1;
        size_t off_hi = off_lo + (size_t)8 * D_;
        float2 o2; o2.x = oacc[n][2] * inv_hi; o2.y = oacc[n][3] * inv_hi;
        *(float2*)(O + off_hi) = o2;
    }
}

// ---------------------------------------------------------------------------
// Launch
// ---------------------------------------------------------------------------
extern "C" void kernel_launch(void* const* d_in, const int* in_sizes, int n_in,
                              void* d_out, int out_size)
{
    const float* x   = (const float*)d_in[0];
    const float* wq  = (const float*)d_in[1];
    const float* wk  = (const float*)d_in[2];
    const float* wv  = (const float*)d_in[3];
    const float* wo  = (const float*)d_in[4];
    const float* w1  = (const float*)d_in[5];
    const float* b1  = (const float*)d_in[6];
    const float* w2  = (const float*)d_in[7];
    const float* b2  = (const float*)d_in[8];
    const float* g1  = (const float*)d_in[9];
    const float* be1 = (const float*)d_in[10];
    const float* g2  = (const float*)d_in[11];
    const float* be2 = (const float*)d_in[12];
    float* out = (float*)d_out;

    float *h, *q, *k, *v, *at, *x1, *h2, *ff;
    cudaGetSymbolAddress((void**)&h,  g_h);
    cudaGetSymbolAddress((void**)&q,  g_q);
    cudaGetSymbolAddress((void**)&k,  g_k);
    cudaGetSymbolAddress((void**)&v,  g_v);
    cudaGetSymbolAddress((void**)&at, g_at);
    cudaGetSymbolAddress((void**)&x1, g_x1);
    cudaGetSymbolAddress((void**)&h2, g_h2);
    cudaGetSymbolAddress((void**)&ff, g_ff);

    // allow >48KB dynamic smem for the attention kernel (host-side attribute,
    // idempotent, legal under graph capture)
    cudaFuncSetAttribute(attn_tc_kernel,
                         cudaFuncAttributeMaxDynamicSharedMemorySize,
                         ATTN_SMEM_BYTES);

    dim3 blk(256);
    dim3 grid_sq(D_ / 128, NTOK / 128);      // [8192 x 1024] tiles
    dim3 grid_ff(DFF_ / 128, NTOK / 128);    // [8192 x 4096] tiles

    // 1) h = LN1(x)
    ln_kernel<<<NTOK, blk>>>(x, g1, be1, h);

    // 2-4) q,k,v projections (tf32 tensor cores)
    tf32gemm_kernel<0><<<grid_sq, blk>>>(NTOK, D_, D_, h, wq, nullptr, nullptr, q);
    tf32gemm_kernel<0><<<grid_sq, blk>>>(NTOK, D_, D_, h, wk, nullptr, nullptr, k);
    tf32gemm_kernel<0><<<grid_sq, blk>>>(NTOK, D_, D_, h, wv, nullptr, nullptr, v);

    // 5) attention (flash, tf32 tensor cores)
    attn_tc_kernel<<<dim3(S_ / 128, B_ * H_), blk, ATTN_SMEM_BYTES>>>(q, k, v, at);

    // 6) x1 = x + attn @ wo
    tf32gemm_kernel<4><<<grid_sq, blk>>>(NTOK, D_, D_, at, wo, nullptr, x, x1);

    // 7) h2 = LN2(x1)
    ln_kernel<<<NTOK, blk>>>(x1, g2, be2, h2);

    // 8) ff = relu(h2 @ w1 + b1)
    tf32gemm_kernel<3><<<grid_ff, blk>>>(NTOK, DFF_, D_, h2, w1, b1, nullptr, ff);

    // 9) out = x1 + ff @ w2 + b2
    tf32gemm_kernel<5><<<grid_sq, blk>>>(NTOK, D_, DFF_, ff, w2, b2, x1, out);
}

// round 12
// speedup vs baseline: 3.2290x; 1.1894x over previous
#include <cuda_runtime.h>
#include <math.h>
#include <stdint.h>

// Problem constants
#define B_   4
#define S_   2048
#define D_   1024
#define H_   16
#define DK_  64
#define DFF_ 4096
#define NTOK (B_*S_)     // 8192 tokens
#define EPS_ 1e-5f

// ---------------------------------------------------------------------------
// Scratch (device globals: allocation-free, allowed by harness rules)
// ---------------------------------------------------------------------------
__device__ float g_h [(size_t)NTOK*D_];   // LN1 output
__device__ float g_q [(size_t)NTOK*D_];
__device__ float g_k [(size_t)NTOK*D_];
__device__ float g_v [(size_t)NTOK*D_];
__device__ float g_at[(size_t)NTOK*D_];
__device__ float g_x1[(size_t)NTOK*D_];
__device__ float g_h2[(size_t)NTOK*D_];
__device__ float g_ff[(size_t)NTOK*DFF_];

// ---------------------------------------------------------------------------
// Common TF32 helpers
// ---------------------------------------------------------------------------
__device__ __forceinline__ uint32_t f2tf32(float f) {
    uint32_t u;
    asm("cvt.rna.tf32.f32 %0, %1;" : "=r"(u) : "f"(f));
    return u;
}

__device__ __forceinline__ void mma_tf32(float* c, const uint32_t* a, const uint32_t* b) {
    asm volatile(
        "mma.sync.aligned.m16n8k8.row.col.f32.tf32.tf32.f32 "
        "{%0,%1,%2,%3}, {%4,%5,%6,%7}, {%8,%9}, {%0,%1,%2,%3};\n"
        : "+f"(c[0]), "+f"(c[1]), "+f"(c[2]), "+f"(c[3])
        : "r"(a[0]), "r"(a[1]), "r"(a[2]), "r"(a[3]),
          "r"(b[0]), "r"(b[1]));
}

// ---------------------------------------------------------------------------
// LayerNorm: one block per row (D=1024, 256 threads, 1 float4/thread)
// ---------------------------------------------------------------------------
__global__ void __launch_bounds__(256) ln_kernel(
    const float* __restrict__ x, const float* __restrict__ g,
    const float* __restrict__ b, float* __restrict__ out)
{
    int row = blockIdx.x;
    int tid = threadIdx.x;
    const float4* xr = (const float4*)(x + (size_t)row * D_);
    float4 xv = xr[tid];

    float s  = xv.x + xv.y + xv.z + xv.w;
    float ss = xv.x*xv.x + xv.y*xv.y + xv.z*xv.z + xv.w*xv.w;

    #pragma unroll
    for (int o = 16; o > 0; o >>= 1) {
        s  += __shfl_xor_sync(0xffffffffu, s,  o);
        ss += __shfl_xor_sync(0xffffffffu, ss, o);
    }
    __shared__ float sh_s[8], sh_ss[8];
    __shared__ float mu_sh, rs_sh;
    if ((tid & 31) == 0) { sh_s[tid >> 5] = s; sh_ss[tid >> 5] = ss; }
    __syncthreads();
    if (tid == 0) {
        float S = 0.f, SS = 0.f;
        #pragma unroll
        for (int i = 0; i < 8; i++) { S += sh_s[i]; SS += sh_ss[i]; }
        float mu  = S / (float)D_;
        float var = SS / (float)D_ - mu * mu;
        mu_sh = mu;
        rs_sh = rsqrtf(var + EPS_);
    }
    __syncthreads();
    float mu = mu_sh, rs = rs_sh;

    const float4* gr = (const float4*)g;
    const float4* br = (const float4*)b;
    float4 gv = gr[tid], bv = br[tid];
    float4 o;
    o.x = (xv.x - mu) * rs * gv.x + bv.x;
    o.y = (xv.y - mu) * rs * gv.y + bv.y;
    o.z = (xv.z - mu) * rs * gv.z + bv.z;
    o.w = (xv.w - mu) * rs * gv.w + bv.w;
    ((float4*)(out + (size_t)row * D_))[tid] = o;
}

// ---------------------------------------------------------------------------
// TF32 tensor-core GEMM, big-tile version.
// Block tile 256(m) x 128(n) x 16(k). 256 threads = 8 warps in 4x2,
// warp tile 64x64 = 4x8 m16n8k8 tiles. Double-buffered dynamic smem:
//   A stored [m][k] stride 20 (conflict-free frag loads, STS.128 fill)
//   B stored [k][n] stride 136 (conflict-free frag loads, STS.128 fill)
// EPI bit0 = +bias[n], bit1 = relu, bit2 = +res[m,n]
// NSEL=3: QKV-fused (B/C selected by n-block group of 8).
// Requires M%256==0, N%128==0, K%16==0.
// ---------------------------------------------------------------------------
#define PAD2  20
#define PADB2 136
#define SM_A (256*PAD2)              // 5120 u32 per stage
#define SM_B (16*PADB2)              // 2176 u32 per stage
#define GSM_U32 (2*SM_A + 2*SM_B)    // 14592
#define GSM_BYTES (GSM_U32*4)        // 58368

template<int EPI, int NSEL>
__global__ void __launch_bounds__(256, 1) tf32gemm256_kernel(
    int M, int N, int K,
    const float* __restrict__ A,
    const float* __restrict__ B0, const float* __restrict__ B1,
    const float* __restrict__ B2,
    const float* __restrict__ bias, const float* __restrict__ res,
    float* __restrict__ C0, float* __restrict__ C1, float* __restrict__ C2)
{
    extern __shared__ __align__(16) uint32_t gsm[];
    uint32_t* As = gsm;               // [2][256][PAD2]
    uint32_t* Bs = gsm + 2 * SM_A;    // [2][16][PADB2]

    int tid  = threadIdx.x;
    int lane = tid & 31;
    int warp = tid >> 5;
    int wm = (warp >> 1) * 64;        // 4 m-slabs
    int wn = (warp & 1) * 64;         // 2 n-slabs
    int m0 = blockIdx.y * 256;
    int tg = lane & 3;
    int gp = lane >> 2;

    const float* Bm;
    float* C;
    int n0;
    if (NSEL == 3) {
        int nb  = blockIdx.x;
        int sel = nb >> 3;
        n0 = (nb & 7) * 128;
        Bm = (sel == 0) ? B0 : (sel == 1) ? B1 : B2;
        C  = (sel == 0) ? C0 : (sel == 1) ? C1 : C2;
    } else {
        n0 = blockIdx.x * 128;
        Bm = B0;
        C  = C0;
    }

    const float* Abase = A + (size_t)m0 * K;
    const float* Bbase = Bm + n0;

    float acc[4][8][4];
    #pragma unroll
    for (int mt = 0; mt < 4; mt++)
        #pragma unroll
        for (int nt = 0; nt < 8; nt++)
            #pragma unroll
            for (int c = 0; c < 4; c++) acc[mt][nt][c] = 0.f;

    float4 aldr[4], bldr[2];

    // A tile 256m x 16k : 1024 float4, 4/thread. m = idx>>2, kq = idx&3.
    // B tile 16k x 128n : 512 float4, 2/thread. k = idx>>5, n4 = idx&31.
    #define LD_A(k0) { _Pragma("unroll") for (int i = 0; i < 4; i++) { \
        int idx = tid + i*256; int m = idx >> 2; int kq = idx & 3;     \
        aldr[i] = *(const float4*)(Abase + (size_t)m * K + (k0) + kq*4); } }
    #define LD_B(k0) { _Pragma("unroll") for (int i = 0; i < 2; i++) { \
        int idx = tid + i*256; int k = idx >> 5; int n4 = idx & 31;    \
        bldr[i] = *(const float4*)(Bbase + (size_t)((k0) + k) * N + n4*4); } }
    #define ST_AB(sg) { _Pragma("unroll") for (int i = 0; i < 4; i++) { \
        int idx = tid + i*256; int m = idx >> 2; int kq = idx & 3;      \
        uint32_t t[4];                                                  \
        t[0] = f2tf32(aldr[i].x); t[1] = f2tf32(aldr[i].y);             \
        t[2] = f2tf32(aldr[i].z); t[3] = f2tf32(aldr[i].w);             \
        *(uint4*)(As + (sg)*SM_A + m*PAD2 + kq*4) = *(uint4*)t; }       \
        _Pragma("unroll") for (int i = 0; i < 2; i++) {                 \
        int idx = tid + i*256; int k = idx >> 5; int n4 = idx & 31;     \
        uint32_t t[4];                                                  \
        t[0] = f2tf32(bldr[i].x); t[1] = f2tf32(bldr[i].y);             \
        t[2] = f2tf32(bldr[i].z); t[3] = f2tf32(bldr[i].w);             \
        *(uint4*)(Bs + (sg)*SM_B + k*PADB2 + n4*4) = *(uint4*)t; } }

    LD_A(0); LD_B(0);
    ST_AB(0);
    __syncthreads();

    int s = 0;
    for (int k0 = 0; k0 < K; k0 += 16) {
        bool more = (k0 + 16) < K;
        if (more) { LD_A(k0 + 16); LD_B(k0 + 16); }

        #pragma unroll
        for (int hf = 0; hf < 16; hf += 8) {
            int kb = hf + tg;
            uint32_t af[4][4];
            #pragma unroll
            for (int mt = 0; mt < 4; mt++) {
                const uint32_t* ap = As + s*SM_A + (wm + mt*16 + gp)*PAD2 + kb;
                af[mt][0] = ap[0];
                af[mt][1] = ap[8*PAD2];
                af[mt][2] = ap[4];
                af[mt][3] = ap[8*PAD2 + 4];
            }
            uint32_t bf[8][2];
            #pragma unroll
            for (int nt = 0; nt < 8; nt++) {
                const uint32_t* bp = Bs + s*SM_B + kb*PADB2 + wn + nt*8 + gp;
                bf[nt][0] = bp[0];
                bf[nt][1] = bp[4*PADB2];
            }
            #pragma unroll
            for (int mt = 0; mt < 4; mt++)
                #pragma unroll
                for (int nt = 0; nt < 8; nt++)
                    mma_tf32(acc[mt][nt], af[mt], bf[nt]);
        }

        if (more) ST_AB(s ^ 1);
        __syncthreads();
        s ^= 1;
    }

    // ---- epilogue ----
    #pragma unroll
    for (int mt = 0; mt < 4; mt++) {
        int row0 = m0 + wm + mt*16 + gp;
        #pragma unroll
        for (int nt = 0; nt < 8; nt++) {
            int col = n0 + wn + nt*8 + tg*2;
            #pragma unroll
            for (int hh = 0; hh < 2; hh++) {
                int r = row0 + hh*8;
                size_t off = (size_t)r * N + col;
                float v0 = acc[mt][nt][hh*2 + 0];
                float v1 = acc[mt][nt][hh*2 + 1];
                if (EPI & 1) { v0 += bias[col]; v1 += bias[col + 1]; }
                if (EPI & 2) { v0 = fmaxf(v0, 0.f); v1 = fmaxf(v1, 0.f); }
                if (EPI & 4) { float2 rv = *(const float2*)(res + off);
                               v0 += rv.x; v1 += rv.y; }
                float2 ov; ov.x = v0; ov.y = v1;
                *(float2*)(C + off) = ov;
            }
        }
    }
    #undef LD_A
    #undef LD_B
    #undef ST_AB
}

// ---------------------------------------------------------------------------
// TF32 tensor-core flash attention (unchanged from R11).
// grid (S/128, B*H), 256 threads (8 warps), BQ=128, BKV=64.
// ---------------------------------------------------------------------------
#define SQS 68
#define SKS 68
#define SVS 72
#define SPS 68
#define OFF_K 8704            // 128*68
#define OFF_V 13056           // + 64*68
#define OFF_P 17664           // + 64*72
#define ATTN_SMEM_U32 26368   // + 128*68
#define ATTN_SMEM_BYTES (ATTN_SMEM_U32 * 4)

__global__ void __launch_bounds__(256, 2) attn_tc_kernel(
    const float* __restrict__ Q, const float* __restrict__ K,
    const float* __restrict__ V, float* __restrict__ O)
{
    extern __shared__ uint32_t smem_u[];
    uint32_t* sQ = smem_u;
    uint32_t* sK = smem_u + OFF_K;
    uint32_t* sV = smem_u + OFF_V;
    uint32_t* sP = smem_u + OFF_P;

    int tid  = threadIdx.x;
    int warp = tid >> 5;
    int lane = tid & 31;
    int gp = lane >> 2;
    int tg = lane & 3;
    int mw = warp * 16;

    int qt = blockIdx.x;
    int bh = blockIdx.y;
    int b  = bh >> 4;
    int h  = bh & 15;
    size_t base = ((size_t)b * S_) * D_ + (size_t)h * DK_;

    for (int i = tid; i < 128 * 16; i += 256) {
        int r = i >> 4, c4 = (i & 15) * 4;
        float4 v = *(const float4*)(Q + base + (size_t)(qt * 128 + r) * D_ + c4);
        uint32_t q4[4];
        q4[0] = f2tf32(v.x * 0.125f); q4[1] = f2tf32(v.y * 0.125f);
        q4[2] = f2tf32(v.z * 0.125f); q4[3] = f2tf32(v.w * 0.125f);
        *(uint4*)(sQ + r * SQS + c4) = *(uint4*)q4;
    }

    float oacc[8][4];
    #pragma unroll
    for (int n = 0; n < 8; n++)
        #pragma unroll
        for (int c = 0; c < 4; c++) oacc[n][c] = 0.f;
    float m_lo = -INFINITY, m_hi = -INFINITY;
    float l_lo = 0.f, l_hi = 0.f;

    for (int kt = 0; kt < S_ / 64; kt++) {
        for (int i = tid; i < 64 * 16; i += 256) {
            int r = i >> 4, c4 = (i & 15) * 4;
            size_t goff = base + (size_t)(kt * 64 + r) * D_ + c4;
            float4 kv = *(const float4*)(K + goff);
            float4 vv = *(const float4*)(V + goff);
            uint32_t k4[4], v4[4];
            k4[0] = f2tf32(kv.x); k4[1] = f2tf32(kv.y);
            k4[2] = f2tf32(kv.z); k4[3] = f2tf32(kv.w);
            v4[0] = f2tf32(vv.x); v4[1] = f2tf32(vv.y);
            v4[2] = f2tf32(vv.z); v4[3] = f2tf32(vv.w);
            *(uint4*)(sK + r * SKS + c4) = *(uint4*)k4;
            *(uint4*)(sV + r * SVS + c4) = *(uint4*)v4;
        }
        __syncthreads();

        float sacc[8][4];
        #pragma unroll
        for (int n = 0; n < 8; n++)
            #pragma unroll
            for (int c = 0; c < 4; c++) sacc[n][c] = 0.f;

        #pragma unroll
        for (int k = 0; k < 8; k++) {
            uint32_t aq[4];
            const uint32_t* qr = sQ + (mw + gp) * SQS + k * 8 + tg;
            aq[0] = qr[0];
            aq[1] = qr[8 * SQS];
            aq[2] = qr[4];
            aq[3] = qr[8 * SQS + 4];
            #pragma unroll
            for (int n = 0; n < 8; n++) {
                uint32_t bk[2];
                const uint32_t* kr = sK + (n * 8 + gp) * SKS + k * 8 + tg;
                bk[0] = kr[0];
                bk[1] = kr[4];
                mma_tf32(sacc[n], aq, bk);
            }
        }

        float mx_lo = -INFINITY, mx_hi = -INFINITY;
        #pragma unroll
        for (int n = 0; n < 8; n++) {
            mx_lo = fmaxf(mx_lo, fmaxf(sacc[n][0], sacc[n][1]));
            mx_hi = fmaxf(mx_hi, fmaxf(sacc[n][2], sacc[n][3]));
        }
        mx_lo = fmaxf(mx_lo, __shfl_xor_sync(0xffffffffu, mx_lo, 1));
        mx_lo = fmaxf(mx_lo, __shfl_xor_sync(0xffffffffu, mx_lo, 2));
        mx_hi = fmaxf(mx_hi, __shfl_xor_sync(0xffffffffu, mx_hi, 1));
        mx_hi = fmaxf(mx_hi, __shfl_xor_sync(0xffffffffu, mx_hi, 2));

        float mn_lo = fmaxf(m_lo, mx_lo);
        float mn_hi = fmaxf(m_hi, mx_hi);
        float f_lo = __expf(m_lo - mn_lo);
        float f_hi = __expf(m_hi - mn_hi);
        m_lo = mn_lo; m_hi = mn_hi;

        float s_lo = 0.f, s_hi = 0.f;
        uint32_t* plo_base = sP + (mw + gp) * SPS + tg * 2;
        #pragma unroll
        for (int n = 0; n < 8; n++) {
            float p0 = __expf(sacc[n][0] - mn_lo);
            float p1 = __expf(sacc[n][1] - mn_lo);
            float p2 = __expf(sacc[n][2] - mn_hi);
            float p3 = __expf(sacc[n][3] - mn_hi);
            s_lo += p0 + p1;
            s_hi += p2 + p3;
            uint32_t* plo = plo_base + n * 8;
            plo[0] = f2tf32(p0); plo[1] = f2tf32(p1);
            plo[8 * SPS] = f2tf32(p2); plo[8 * SPS + 1] = f2tf32(p3);
        }
        s_lo += __shfl_xor_sync(0xffffffffu, s_lo, 1);
        s_lo += __shfl_xor_sync(0xffffffffu, s_lo, 2);
        s_hi += __shfl_xor_sync(0xffffffffu, s_hi, 1);
        s_hi += __shfl_xor_sync(0xffffffffu, s_hi, 2);
        l_lo = l_lo * f_lo + s_lo;
        l_hi = l_hi * f_hi + s_hi;

        #pragma unroll
        for (int n = 0; n < 8; n++) {
            oacc[n][0] *= f_lo; oacc[n][1] *= f_lo;
            oacc[n][2] *= f_hi; oacc[n][3] *= f_hi;
        }

        __syncwarp();

        #pragma unroll
        for (int k = 0; k < 8; k++) {
            uint32_t ap[4];
            const uint32_t* pr = sP + (mw + gp) * SPS + k * 8 + tg;
            ap[0] = pr[0];
            ap[1] = pr[8 * SPS];
            ap[2] = pr[4];
            ap[3] = pr[8 * SPS + 4];
            #pragma unroll
            for (int n = 0; n < 8; n++) {
                uint32_t bv[2];
                const uint32_t* vr = sV + (k * 8 + tg) * SVS + n * 8 + gp;
                bv[0] = vr[0];
                bv[1] = vr[4 * SVS];
                mma_tf32(oacc[n], ap, bv);
            }
        }
        __syncthreads();
    }

    float inv_lo = 1.f / l_lo;
    float inv_hi = 1.f / l_hi;
    int row_lo = qt * 128 + mw + gp;
    #pragma unroll
    for (int n = 0; n < 8; n++) {
        size_t off_lo = base + (size_t)row_lo * D_ + n * 8 + tg * 2;
        float2 o1; o1.x = oacc[n][0] * inv_lo; o1.y = oacc[n][1] * inv_lo;
        *(float2*)(O + off_lo) = o1;
        size_t off_hi = off_lo + (size_t)8 * D_;
        float2 o2; o2.x = oacc[n][2] * inv_hi; o2.y = oacc[n][3] * inv_hi;
        *(float2*)(O + off_hi) = o2;
    }
}

// ---------------------------------------------------------------------------
// Launch
// ---------------------------------------------------------------------------
extern "C" void kernel_launch(void* const* d_in, const int* in_sizes, int n_in,
                              void* d_out, int out_size)
{
    const float* x   = (const float*)d_in[0];
    const float* wq  = (const float*)d_in[1];
    const float* wk  = (const float*)d_in[2];
    const float* wv  = (const float*)d_in[3];
    const float* wo  = (const float*)d_in[4];
    const float* w1  = (const float*)d_in[5];
    const float* b1  = (const float*)d_in[6];
    const float* w2  = (const float*)d_in[7];
    const float* b2  = (const float*)d_in[8];
    const float* g1  = (const float*)d_in[9];
    const float* be1 = (const float*)d_in[10];
    const float* g2  = (const float*)d_in[11];
    const float* be2 = (const float*)d_in[12];
    float* out = (float*)d_out;

    float *h, *q, *k, *v, *at, *x1, *h2, *ff;
    cudaGetSymbolAddress((void**)&h,  g_h);
    cudaGetSymbolAddress((void**)&q,  g_q);
    cudaGetSymbolAddress((void**)&k,  g_k);
    cudaGetSymbolAddress((void**)&v,  g_v);
    cudaGetSymbolAddress((void**)&at, g_at);
    cudaGetSymbolAddress((void**)&x1, g_x1);
    cudaGetSymbolAddress((void**)&h2, g_h2);
    cudaGetSymbolAddress((void**)&ff, g_ff);

    // >48KB dynamic smem opt-ins (host-side attributes, idempotent)
    cudaFuncSetAttribute(attn_tc_kernel,
                         cudaFuncAttributeMaxDynamicSharedMemorySize,
                         ATTN_SMEM_BYTES);
    cudaFuncSetAttribute(tf32gemm256_kernel<0,3>,
                         cudaFuncAttributeMaxDynamicSharedMemorySize, GSM_BYTES);
    cudaFuncSetAttribute(tf32gemm256_kernel<4,1>,
                         cudaFuncAttributeMaxDynamicSharedMemorySize, GSM_BYTES);
    cudaFuncSetAttribute(tf32gemm256_kernel<3,1>,
                         cudaFuncAttributeMaxDynamicSharedMemorySize, GSM_BYTES);
    cudaFuncSetAttribute(tf32gemm256_kernel<5,1>,
                         cudaFuncAttributeMaxDynamicSharedMemorySize, GSM_BYTES);

    dim3 blk(256);

    // 1) h = LN1(x)
    ln_kernel<<<NTOK, blk>>>(x, g1, be1, h);

    // 2-4) q,k,v projections: fused QKV (weight/output selected per n-block)
    tf32gemm256_kernel<0,3><<<dim3(24, NTOK/256), blk, GSM_BYTES>>>(
        NTOK, D_, D_, h, wq, wk, wv, nullptr, nullptr, q, k, v);

    // 5) attention (flash, tf32 tensor cores)
    attn_tc_kernel<<<dim3(S_ / 128, B_ * H_), blk, ATTN_SMEM_BYTES>>>(q, k, v, at);

    // 6) x1 = x + attn @ wo
    tf32gemm256_kernel<4,1><<<dim3(D_/128, NTOK/256), blk, GSM_BYTES>>>(
        NTOK, D_, D_, at, wo, nullptr, nullptr, nullptr, x, x1, nullptr, nullptr);

    // 7) h2 = LN2(x1)
    ln_kernel<<<NTOK, blk>>>(x1, g2, be2, h2);

    // 8) ff = relu(h2 @ w1 + b1)
    tf32gemm256_kernel<3,1><<<dim3(DFF_/128, NTOK/256), blk, GSM_BYTES>>>(
        NTOK, DFF_, D_, h2, w1, nullptr, nullptr, b1, nullptr, ff, nullptr, nullptr);

    // 9) out = x1 + ff @ w2 + b2
    tf32gemm256_kernel<5,1><<<dim3(D_/128, NTOK/256), blk, GSM_BYTES>>>(
        NTOK, D_, DFF_, ff, w2, nullptr, nullptr, b2, x1, out, nullptr, nullptr);
}

// round 14
// speedup vs baseline: 3.3742x; 1.0450x over previous
#include <cuda_runtime.h>
#include <math.h>
#include <stdint.h>

// Problem constants
#define B_   4
#define S_   2048
#define D_   1024
#define H_   16
#define DK_  64
#define DFF_ 4096
#define NTOK (B_*S_)     // 8192 tokens
#define EPS_ 1e-5f

// ---------------------------------------------------------------------------
// Scratch (device globals: allocation-free, allowed by harness rules)
// ---------------------------------------------------------------------------
__device__ float g_h [(size_t)NTOK*D_];   // LN1 output
__device__ float g_q [(size_t)NTOK*D_];
__device__ float g_k [(size_t)NTOK*D_];
__device__ float g_v [(size_t)NTOK*D_];
__device__ float g_at[(size_t)NTOK*D_];
__device__ float g_x1[(size_t)NTOK*D_];
__device__ float g_h2[(size_t)NTOK*D_];
__device__ float g_ff[(size_t)NTOK*DFF_];

// ---------------------------------------------------------------------------
// Common TF32 helpers
// ---------------------------------------------------------------------------
__device__ __forceinline__ uint32_t f2tf32(float f) {
    uint32_t u;
    asm("cvt.rna.tf32.f32 %0, %1;" : "=r"(u) : "f"(f));
    return u;
}

__device__ __forceinline__ void mma_tf32(float* c, const uint32_t* a, const uint32_t* b) {
    asm volatile(
        "mma.sync.aligned.m16n8k8.row.col.f32.tf32.tf32.f32 "
        "{%0,%1,%2,%3}, {%4,%5,%6,%7}, {%8,%9}, {%0,%1,%2,%3};\n"
        : "+f"(c[0]), "+f"(c[1]), "+f"(c[2]), "+f"(c[3])
        : "r"(a[0]), "r"(a[1]), "r"(a[2]), "r"(a[3]),
          "r"(b[0]), "r"(b[1]));
}

__device__ __forceinline__ void cp16(uint32_t saddr, const float* g) {
    asm volatile("cp.async.ca.shared.global [%0], [%1], 16;\n"
                 :: "r"(saddr), "l"(g));
}

// ---------------------------------------------------------------------------
// LayerNorm: one block per row (D=1024, 256 threads, 1 float4/thread)
// ---------------------------------------------------------------------------
__global__ void __launch_bounds__(256) ln_kernel(
    const float* __restrict__ x, const float* __restrict__ g,
    const float* __restrict__ b, float* __restrict__ out)
{
    int row = blockIdx.x;
    int tid = threadIdx.x;
    const float4* xr = (const float4*)(x + (size_t)row * D_);
    float4 xv = xr[tid];

    float s  = xv.x + xv.y + xv.z + xv.w;
    float ss = xv.x*xv.x + xv.y*xv.y + xv.z*xv.z + xv.w*xv.w;

    #pragma unroll
    for (int o = 16; o > 0; o >>= 1) {
        s  += __shfl_xor_sync(0xffffffffu, s,  o);
        ss += __shfl_xor_sync(0xffffffffu, ss, o);
    }
    __shared__ float sh_s[8], sh_ss[8];
    __shared__ float mu_sh, rs_sh;
    if ((tid & 31) == 0) { sh_s[tid >> 5] = s; sh_ss[tid >> 5] = ss; }
    __syncthreads();
    if (tid == 0) {
        float S = 0.f, SS = 0.f;
        #pragma unroll
        for (int i = 0; i < 8; i++) { S += sh_s[i]; SS += sh_ss[i]; }
        float mu  = S / (float)D_;
        float var = SS / (float)D_ - mu * mu;
        mu_sh = mu;
        rs_sh = rsqrtf(var + EPS_);
    }
    __syncthreads();
    float mu = mu_sh, rs = rs_sh;

    const float4* gr = (const float4*)g;
    const float4* br = (const float4*)b;
    float4 gv = gr[tid], bv = br[tid];
    float4 o;
    o.x = (xv.x - mu) * rs * gv.x + bv.x;
    o.y = (xv.y - mu) * rs * gv.y + bv.y;
    o.z = (xv.z - mu) * rs * gv.z + bv.z;
    o.w = (xv.w - mu) * rs * gv.w + bv.w;
    ((float4*)(out + (size_t)row * D_))[tid] = o;
}

// ---------------------------------------------------------------------------
// TF32 tensor-core GEMM, cp.async 4-stage pipeline.
// Block tile 256(m) x 128(n) x 16(k). 256 threads = 8 warps in 4x2,
// warp tile 64x64 = 4x8 m16n8k8 tiles.
//   A smem [m][k] stride 20 (u32), filled by cp.async 16B (raw f32)
//   B smem [k][n] stride 136 (u32), filled by cp.async 16B (raw f32)
// MMA consumes raw f32 bits as tf32 (implicit truncation).
// EPI bit0 = +bias[n], bit1 = relu, bit2 = +res[m,n]
// NSEL=3: QKV-fused (B/C selected by n-block group of 8).
// ---------------------------------------------------------------------------
#define STAGES 4
#define PAD2  20
#define PADB2 136
#define SM_A (256*PAD2)                  // 5120 u32 per stage
#define SM_B (16*PADB2)                  // 2176 u32 per stage
#define GSM_U32 (STAGES*(SM_A + SM_B))   // 29184
#define GSM_BYTES (GSM_U32*4)            // 116736

template<int EPI, int NSEL>
__global__ void __launch_bounds__(256, 1) tf32gemm256_kernel(
    int M, int N, int K,
    const float* __restrict__ A,
    const float* __restrict__ B0, const float* __restrict__ B1,
    const float* __restrict__ B2,
    const float* __restrict__ bias, const float* __restrict__ res,
    float* __restrict__ C0, float* __restrict__ C1, float* __restrict__ C2)
{
    extern __shared__ __align__(16) uint32_t gsm[];
    uint32_t* As = gsm;                       // [STAGES][256][PAD2]
    uint32_t* Bs = gsm + STAGES * SM_A;       // [STAGES][16][PADB2]
    uint32_t sA_base = (uint32_t)__cvta_generic_to_shared(As);
    uint32_t sB_base = (uint32_t)__cvta_generic_to_shared(Bs);

    int tid  = threadIdx.x;
    int lane = tid & 31;
    int warp = tid >> 5;
    int wm = (warp >> 1) * 64;        // 4 m-slabs
    int wn = (warp & 1) * 64;         // 2 n-slabs
    int m0 = blockIdx.y * 256;
    int tg = lane & 3;
    int gp = lane >> 2;

    const float* Bm;
    float* C;
    int n0;
    if (NSEL == 3) {
        int nb  = blockIdx.x;
        int sel = nb >> 3;
        n0 = (nb & 7) * 128;
        Bm = (sel == 0) ? B0 : (sel == 1) ? B1 : B2;
        C  = (sel == 0) ? C0 : (sel == 1) ? C1 : C2;
    } else {
        n0 = blockIdx.x * 128;
        Bm = B0;
        C  = C0;
    }

    const float* Abase = A + (size_t)m0 * K;
    const float* Bbase = Bm + n0;

    float acc[4][8][4];
    #pragma unroll
    for (int mt = 0; mt < 4; mt++)
        #pragma unroll
        for (int nt = 0; nt < 8; nt++)
            #pragma unroll
            for (int c = 0; c < 4; c++) acc[mt][nt][c] = 0.f;

    // issue one stage's cp.async transfers (A: 4x16B, B: 2x16B per thread)
    #define PREFETCH(stage, k0) do {                                          \
        if ((k0) < K) {                                                       \
            _Pragma("unroll") for (int i = 0; i < 4; i++) {                   \
                int idx = tid + i*256; int m = idx >> 2; int kq = idx & 3;    \
                cp16(sA_base + (uint32_t)(((stage)*SM_A + m*PAD2 + kq*4)*4),  \
                     Abase + (size_t)m * K + (k0) + kq*4);                    \
            }                                                                 \
            _Pragma("unroll") for (int i = 0; i < 2; i++) {                   \
                int idx = tid + i*256; int k = idx >> 5; int n4 = idx & 31;   \
                cp16(sB_base + (uint32_t)(((stage)*SM_B + k*PADB2 + n4*4)*4), \
                     Bbase + (size_t)((k0) + k) * N + n4*4);                  \
            }                                                                 \
        }                                                                     \
        asm volatile("cp.async.commit_group;\n" ::: "memory");                \
    } while (0)

    // prologue: stages 0..STAGES-2 in flight
    PREFETCH(0, 0);
    PREFETCH(1, 16);
    PREFETCH(2, 32);

    int niter = K / 16;
    for (int it = 0; it < niter; it++) {
        // wait until the stage we're about to compute has landed
        asm volatile("cp.async.wait_group %0;\n" :: "n"(STAGES - 2) : "memory");
        __syncthreads();

        // refill the stage freed at iteration it-1
        PREFETCH((it + STAGES - 1) & 3, (it + STAGES - 1) * 16);

        int s = it & 3;
        const uint32_t* Asl = As + s * SM_A;
        const uint32_t* Bsl = Bs + s * SM_B;

        #pragma unroll
        for (int hf = 0; hf < 16; hf += 8) {
            int kb = hf + tg;
            uint32_t af[4][4];
            #pragma unroll
            for (int mt = 0; mt < 4; mt++) {
                const uint32_t* ap = Asl + (wm + mt*16 + gp)*PAD2 + kb;
                af[mt][0] = ap[0];
                af[mt][1] = ap[8*PAD2];
                af[mt][2] = ap[4];
                af[mt][3] = ap[8*PAD2 + 4];
            }
            uint32_t bf[8][2];
            #pragma unroll
            for (int nt = 0; nt < 8; nt++) {
                const uint32_t* bp = Bsl + kb*PADB2 + wn + nt*8 + gp;
                bf[nt][0] = bp[0];
                bf[nt][1] = bp[4*PADB2];
            }
            #pragma unroll
            for (int mt = 0; mt < 4; mt++)
                #pragma unroll
                for (int nt = 0; nt < 8; nt++)
                    mma_tf32(acc[mt][nt], af[mt], bf[nt]);
        }
    }
    #undef PREFETCH

    // ---- epilogue ----
    #pragma unroll
    for (int mt = 0; mt < 4; mt++) {
        int row0 = m0 + wm + mt*16 + gp;
        #pragma unroll
        for (int nt = 0; nt < 8; nt++) {
            int col = n0 + wn + nt*8 + tg*2;
            #pragma unroll
            for (int hh = 0; hh < 2; hh++) {
                int r = row0 + hh*8;
                size_t off = (size_t)r * N + col;
                float v0 = acc[mt][nt][hh*2 + 0];
                float v1 = acc[mt][nt][hh*2 + 1];
                if (EPI & 1) { v0 += bias[col]; v1 += bias[col + 1]; }
                if (EPI & 2) { v0 = fmaxf(v0, 0.f); v1 = fmaxf(v1, 0.f); }
                if (EPI & 4) { float2 rv = *(const float2*)(res + off);
                               v0 += rv.x; v1 += rv.y; }
                float2 ov; ov.x = v0; ov.y = v1;
                *(float2*)(C + off) = ov;
            }
        }
    }
}

// ---------------------------------------------------------------------------
// TF32 tensor-core flash attention (unchanged from R12).
// grid (S/128, B*H), 256 threads (8 warps), BQ=128, BKV=64.
// ---------------------------------------------------------------------------
#define SQS 68
#define SKS 68
#define SVS 72
#define SPS 68
#define OFF_K 8704            // 128*68
#define OFF_V 13056           // + 64*68
#define OFF_P 17664           // + 64*72
#define ATTN_SMEM_U32 26368   // + 128*68
#define ATTN_SMEM_BYTES (ATTN_SMEM_U32 * 4)

__global__ void __launch_bounds__(256, 2) attn_tc_kernel(
    const float* __restrict__ Q, const float* __restrict__ K,
    const float* __restrict__ V, float* __restrict__ O)
{
    extern __shared__ uint32_t smem_u[];
    uint32_t* sQ = smem_u;
    uint32_t* sK = smem_u + OFF_K;
    uint32_t* sV = smem_u + OFF_V;
    uint32_t* sP = smem_u + OFF_P;

    int tid  = threadIdx.x;
    int warp = tid >> 5;
    int lane = tid & 31;
    int gp = lane >> 2;
    int tg = lane & 3;
    int mw = warp * 16;

    int qt = blockIdx.x;
    int bh = blockIdx.y;
    int b  = bh >> 4;
    int h  = bh & 15;
    size_t base = ((size_t)b * S_) * D_ + (size_t)h * DK_;

    for (int i = tid; i < 128 * 16; i += 256) {
        int r = i >> 4, c4 = (i & 15) * 4;
        float4 v = *(const float4*)(Q + base + (size_t)(qt * 128 + r) * D_ + c4);
        uint32_t q4[4];
        q4[0] = f2tf32(v.x * 0.125f); q4[1] = f2tf32(v.y * 0.125f);
        q4[2] = f2tf32(v.z * 0.125f); q4[3] = f2tf32(v.w * 0.125f);
        *(uint4*)(sQ + r * SQS + c4) = *(uint4*)q4;
    }

    float oacc[8][4];
    #pragma unroll
    for (int n = 0; n < 8; n++)
        #pragma unroll
        for (int c = 0; c < 4; c++) oacc[n][c] = 0.f;
    float m_lo = -INFINITY, m_hi = -INFINITY;
    float l_lo = 0.f, l_hi = 0.f;

    for (int kt = 0; kt < S_ / 64; kt++) {
        for (int i = tid; i < 64 * 16; i += 256) {
            int r = i >> 4, c4 = (i & 15) * 4;
            size_t goff = base + (size_t)(kt * 64 + r) * D_ + c4;
            float4 kv = *(const float4*)(K + goff);
            float4 vv = *(const float4*)(V + goff);
            uint32_t k4[4], v4[4];
            k4[0] = f2tf32(kv.x); k4[1] = f2tf32(kv.y);
            k4[2] = f2tf32(kv.z); k4[3] = f2tf32(kv.w);
            v4[0] = f2tf32(vv.x); v4[1] = f2tf32(vv.y);
            v4[2] = f2tf32(vv.z); v4[3] = f2tf32(vv.w);
            *(uint4*)(sK + r * SKS + c4) = *(uint4*)k4;
            *(uint4*)(sV + r * SVS + c4) = *(uint4*)v4;
        }
        __syncthreads();

        float sacc[8][4];
        #pragma unroll
        for (int n = 0; n < 8; n++)
            #pragma unroll
            for (int c = 0; c < 4; c++) sacc[n][c] = 0.f;

        #pragma unroll
        for (int k = 0; k < 8; k++) {
            uint32_t aq[4];
            const uint32_t* qr = sQ + (mw + gp) * SQS + k * 8 + tg;
            aq[0] = qr[0];
            aq[1] = qr[8 * SQS];
            aq[2] = qr[4];
            aq[3] = qr[8 * SQS + 4];
            #pragma unroll
            for (int n = 0; n < 8; n++) {
                uint32_t bk[2];
                const uint32_t* kr = sK + (n * 8 + gp) * SKS + k * 8 + tg;
                bk[0] = kr[0];
                bk[1] = kr[4];
                mma_tf32(sacc[n], aq, bk);
            }
        }

        float mx_lo = -INFINITY, mx_hi = -INFINITY;
        #pragma unroll
        for (int n = 0; n < 8; n++) {
            mx_lo = fmaxf(mx_lo, fmaxf(sacc[n][0], sacc[n][1]));
            mx_hi = fmaxf(mx_hi, fmaxf(sacc[n][2], sacc[n][3]));
        }
        mx_lo = fmaxf(mx_lo, __shfl_xor_sync(0xffffffffu, mx_lo, 1));
        mx_lo = fmaxf(mx_lo, __shfl_xor_sync(0xffffffffu, mx_lo, 2));
        mx_hi = fmaxf(mx_hi, __shfl_xor_sync(0xffffffffu, mx_hi, 1));
        mx_hi = fmaxf(mx_hi, __shfl_xor_sync(0xffffffffu, mx_hi, 2));

        float mn_lo = fmaxf(m_lo, mx_lo);
        float mn_hi = fmaxf(m_hi, mx_hi);
        float f_lo = __expf(m_lo - mn_lo);
        float f_hi = __expf(m_hi - mn_hi);
        m_lo = mn_lo; m_hi = mn_hi;

        float s_lo = 0.f, s_hi = 0.f;
        uint32_t* plo_base = sP + (mw + gp) * SPS + tg * 2;
        #pragma unroll
        for (int n = 0; n < 8; n++) {
            float p0 = __expf(sacc[n][0] - mn_lo);
            float p1 = __expf(sacc[n][1] - mn_lo);
            float p2 = __expf(sacc[n][2] - mn_hi);
            float p3 = __expf(sacc[n][3] - mn_hi);
            s_lo += p0 + p1;
            s_hi += p2 + p3;
            uint32_t* plo = plo_base + n * 8;
            plo[0] = f2tf32(p0); plo[1] = f2tf32(p1);
            plo[8 * SPS] = f2tf32(p2); plo[8 * SPS + 1] = f2tf32(p3);
        }
        s_lo += __shfl_xor_sync(0xffffffffu, s_lo, 1);
        s_lo += __shfl_xor_sync(0xffffffffu, s_lo, 2);
        s_hi += __shfl_xor_sync(0xffffffffu, s_hi, 1);
        s_hi += __shfl_xor_sync(0xffffffffu, s_hi, 2);
        l_lo = l_lo * f_lo + s_lo;
        l_hi = l_hi * f_hi + s_hi;

        #pragma unroll
        for (int n = 0; n < 8; n++) {
            oacc[n][0] *= f_lo; oacc[n][1] *= f_lo;
            oacc[n][2] *= f_hi; oacc[n][3] *= f_hi;
        }

        __syncwarp();

        #pragma unroll
        for (int k = 0; k < 8; k++) {
            uint32_t ap[4];
            const uint32_t* pr = sP + (mw + gp) * SPS + k * 8 + tg;
            ap[0] = pr[0];
            ap[1] = pr[8 * SPS];
            ap[2] = pr[4];
            ap[3] = pr[8 * SPS + 4];
            #pragma unroll
            for (int n = 0; n < 8; n++) {
                uint32_t bv[2];
                const uint32_t* vr = sV + (k * 8 + tg) * SVS + n * 8 + gp;
                bv[0] = vr[0];
                bv[1] = vr[4 * SVS];
                mma_tf32(oacc[n], ap, bv);
            }
        }
        __syncthreads();
    }

    float inv_lo = 1.f / l_lo;
    float inv_hi = 1.f / l_hi;
    int row_lo = qt * 128 + mw + gp;
    #pragma unroll
    for (int n = 0; n < 8; n++) {
        size_t off_lo = base + (size_t)row_lo * D_ + n * 8 + tg * 2;
        float2 o1; o1.x = oacc[n][0] * inv_lo; o1.y = oacc[n][1] * inv_lo;
        *(float2*)(O + off_lo) = o1;
        size_t off_hi = off_lo + (size_t)8 * D_;
        float2 o2; o2.x = oacc[n][2] * inv_hi; o2.y = oacc[n][3] * inv_hi;
        *(float2*)(O + off_hi) = o2;
    }
}

// ---------------------------------------------------------------------------
// Launch
// ---------------------------------------------------------------------------
extern "C" void kernel_launch(void* const* d_in, const int* in_sizes, int n_in,
                              void* d_out, int out_size)
{
    const float* x   = (const float*)d_in[0];
    const float* wq  = (const float*)d_in[1];
    const float* wk  = (const float*)d_in[2];
    const float* wv  = (const float*)d_in[3];
    const float* wo  = (const float*)d_in[4];
    const float* w1  = (const float*)d_in[5];
    const float* b1  = (const float*)d_in[6];
    const float* w2  = (const float*)d_in[7];
    const float* b2  = (const float*)d_in[8];
    const float* g1  = (const float*)d_in[9];
    const float* be1 = (const float*)d_in[10];
    const float* g2  = (const float*)d_in[11];
    const float* be2 = (const float*)d_in[12];
    float* out = (float*)d_out;

    float *h, *q, *k, *v, *at, *x1, *h2, *ff;
    cudaGetSymbolAddress((void**)&h,  g_h);
    cudaGetSymbolAddress((void**)&q,  g_q);
    cudaGetSymbolAddress((void**)&k,  g_k);
    cudaGetSymbolAddress((void**)&v,  g_v);
    cudaGetSymbolAddress((void**)&at, g_at);
    cudaGetSymbolAddress((void**)&x1, g_x1);
    cudaGetSymbolAddress((void**)&h2, g_h2);
    cudaGetSymbolAddress((void**)&ff, g_ff);

    // >48KB dynamic smem opt-ins (host-side attributes, idempotent)
    cudaFuncSetAttribute(attn_tc_kernel,
                         cudaFuncAttributeMaxDynamicSharedMemorySize,
                         ATTN_SMEM_BYTES);
    cudaFuncSetAttribute(tf32gemm256_kernel<0,3>,
                         cudaFuncAttributeMaxDynamicSharedMemorySize, GSM_BYTES);
    cudaFuncSetAttribute(tf32gemm256_kernel<4,1>,
                         cudaFuncAttributeMaxDynamicSharedMemorySize, GSM_BYTES);
    cudaFuncSetAttribute(tf32gemm256_kernel<3,1>,
                         cudaFuncAttributeMaxDynamicSharedMemorySize, GSM_BYTES);
    cudaFuncSetAttribute(tf32gemm256_kernel<5,1>,
                         cudaFuncAttributeMaxDynamicSharedMemorySize, GSM_BYTES);

    dim3 blk(256);

    // 1) h = LN1(x)
    ln_kernel<<<NTOK, blk>>>(x, g1, be1, h);

    // 2-4) q,k,v projections: fused QKV (weight/output selected per n-block)
    tf32gemm256_kernel<0,3><<<dim3(24, NTOK/256), blk, GSM_BYTES>>>(
        NTOK, D_, D_, h, wq, wk, wv, nullptr, nullptr, q, k, v);

    // 5) attention (flash, tf32 tensor cores)
    attn_tc_kernel<<<dim3(S_ / 128, B_ * H_), blk, ATTN_SMEM_BYTES>>>(q, k, v, at);

    // 6) x1 = x + attn @ wo
    tf32gemm256_kernel<4,1><<<dim3(D_/128, NTOK/256), blk, GSM_BYTES>>>(
        NTOK, D_, D_, at, wo, nullptr, nullptr, nullptr, x, x1, nullptr, nullptr);

    // 7) h2 = LN2(x1)
    ln_kernel<<<NTOK, blk>>>(x1, g2, be2, h2);

    // 8) ff = relu(h2 @ w1 + b1)
    tf32gemm256_kernel<3,1><<<dim3(DFF_/128, NTOK/256), blk, GSM_BYTES>>>(
        NTOK, DFF_, D_, h2, w1, nullptr, nullptr, b1, nullptr, ff, nullptr, nullptr);

    // 9) out = x1 + ff @ w2 + b2
    tf32gemm256_kernel<5,1><<<dim3(D_/128, NTOK/256), blk, GSM_BYTES>>>(
        NTOK, D_, DFF_, ff, w2, nullptr, nullptr, b2, x1, out, nullptr, nullptr);
}